// round 10
// baseline (speedup 1.0000x reference)
#include <cuda_runtime.h>
#include <cuda_bf16.h>
#include <cuda_fp16.h>
#include <math.h>
#include <stdint.h>

#define DD   128
#define MAXN 50000
#define MAXE 800000

// Scratch (allocation-free rule: __device__ globals)
__device__ __align__(16) float   g_dinv[MAXN];
__device__ __align__(16) __half  g_hbuf[(size_t)MAXN * DD];  // fp16 messages
__device__ __align__(16) float   g_buf2[(size_t)MAXN * DD];  // fp32 activation
__device__ __align__(16) int     g_cnt[MAXN];
__device__ __align__(16) int     g_rowptr[MAXN + 4];
__device__ __align__(16) int     g_cur[MAXN];
__device__ __align__(16) int     g_col[MAXE];
__device__ __align__(16) int     g_part[64];
// Pre-split/transposed/swizzled W images (one per layer):
// [kh0: Bhi 16KB | Blo 16KB][kh1: Bhi 16KB | Blo 16KB]  (Bt[n][k] bf16, SW128)
__device__ __align__(16) uint8_t g_wb1[65536];
__device__ __align__(16) uint8_t g_wb2[65536];

// ---------------------------------------------------------------------------
// Helpers (sm_80+ only: ldmatrix + mma.sync — NO tcgen05, target is sm_103)
// ---------------------------------------------------------------------------
__device__ __forceinline__ uint32_t swz128(uint32_t off) {
    return off ^ ((off >> 3) & 0x70);
}
__device__ __forceinline__ uint32_t smem_u32(const void* p) {
    return (uint32_t)__cvta_generic_to_shared(p);
}

__device__ __forceinline__ void ldsm_x4(uint32_t& r0, uint32_t& r1,
                                        uint32_t& r2, uint32_t& r3, uint32_t addr) {
    asm volatile("ldmatrix.sync.aligned.m8n8.x4.shared.b16 {%0,%1,%2,%3}, [%4];"
                 : "=r"(r0), "=r"(r1), "=r"(r2), "=r"(r3) : "r"(addr));
}
__device__ __forceinline__ void ldsm_x2(uint32_t& r0, uint32_t& r1, uint32_t addr) {
    asm volatile("ldmatrix.sync.aligned.m8n8.x2.shared.b16 {%0,%1}, [%2];"
                 : "=r"(r0), "=r"(r1) : "r"(addr));
}
__device__ __forceinline__ void mma_bf16(float& d0, float& d1, float& d2, float& d3,
                                         uint32_t a0, uint32_t a1, uint32_t a2, uint32_t a3,
                                         uint32_t b0, uint32_t b1) {
    asm volatile(
        "mma.sync.aligned.m16n8k16.row.col.f32.bf16.bf16.f32 "
        "{%0,%1,%2,%3}, {%4,%5,%6,%7}, {%8,%9}, {%0,%1,%2,%3};"
        : "+f"(d0), "+f"(d1), "+f"(d2), "+f"(d3)
        : "r"(a0), "r"(a1), "r"(a2), "r"(a3), "r"(b0), "r"(b1));
}

// ---------------------------------------------------------------------------
// W split helper (shared by the fused hist+wprep kernel)
// ---------------------------------------------------------------------------
__device__ __forceinline__ void wprep_one(const float* __restrict__ W,
                                          uint8_t* __restrict__ wb, int idx) {
    int nn = idx & 127;           // output col -> Bt row
    int k  = idx >> 7;            // input dim  -> Bt col
    float v = W[k * DD + nn];
    __nv_bfloat16 hi = __float2bfloat16(v);
    __nv_bfloat16 lo = __float2bfloat16(v - __bfloat162float(hi));
    int half = k >> 6, kk = k & 63;
    uint32_t off = swz128((uint32_t)(nn * 128 + kk * 2));
    *(__nv_bfloat16*)(wb + half * 32768 + off)         = hi;
    *(__nv_bfloat16*)(wb + half * 32768 + 16384 + off) = lo;
}

// ---------------------------------------------------------------------------
// Fused: histogram of dst (blocks < eb, 8 edges/thread) + W1/W2 prep
// ---------------------------------------------------------------------------
__global__ void k_hist_wprep(const int* __restrict__ dst, int* __restrict__ cnt,
                             int E, int eb,
                             const float* __restrict__ W1, uint8_t* __restrict__ wb1,
                             const float* __restrict__ W2, uint8_t* __restrict__ wb2) {
    int b = blockIdx.x;
    if (b < eb) {
        int i = (b * blockDim.x + threadIdx.x) * 8;
        if (i + 7 < E) {
            int4 d0 = *(const int4*)(dst + i);
            int4 d1 = *(const int4*)(dst + i + 4);
            atomicAdd(&cnt[d0.x], 1);
            atomicAdd(&cnt[d0.y], 1);
            atomicAdd(&cnt[d0.z], 1);
            atomicAdd(&cnt[d0.w], 1);
            atomicAdd(&cnt[d1.x], 1);
            atomicAdd(&cnt[d1.y], 1);
            atomicAdd(&cnt[d1.z], 1);
            atomicAdd(&cnt[d1.w], 1);
        } else {
            for (int j = 0; j < 8; j++)
                if (i + j < E) atomicAdd(&cnt[dst[i + j]], 1);
        }
    } else if (b < eb + 64) {
        wprep_one(W1, wb1, (b - eb) * 256 + threadIdx.x);
    } else {
        wprep_one(W2, wb2, (b - eb - 64) * 256 + threadIdx.x);
    }
}

// ---------------------------------------------------------------------------
// 2-phase exclusive scan (+ dinv epilogue). Phase 1: per-block (1024) sums.
// ---------------------------------------------------------------------------
__global__ __launch_bounds__(256) void k_scan_partial(const int* __restrict__ cnt,
                                                      int* __restrict__ part, int n) {
    __shared__ int sh[8];
    int tid  = threadIdx.x;
    int base = blockIdx.x * 1024 + tid * 4;
    int s = 0;
    if (base + 3 < n) {
        int4 v = *(const int4*)(cnt + base);
        s = v.x + v.y + v.z + v.w;
    } else {
        for (int j = 0; j < 4; j++)
            if (base + j < n) s += cnt[base + j];
    }
#pragma unroll
    for (int o = 16; o; o >>= 1) s += __shfl_down_sync(0xffffffffu, s, o);
    if ((tid & 31) == 0) sh[tid >> 5] = s;
    __syncthreads();
    if (tid < 8) {
        s = sh[tid];
#pragma unroll
        for (int o = 4; o; o >>= 1) s += __shfl_down_sync(0x000000ffu, s, o);
        if (tid == 0) part[blockIdx.x] = s;
    }
}

// Phase 2 (fused tops-scan): every block redundantly scans the <=64 partials
// in-register, takes its own exclusive offset, then does the downsweep.
__global__ __launch_bounds__(256) void k_scan_down(const int* __restrict__ cnt,
                                                   const int* __restrict__ part,
                                                   int* __restrict__ rowptr,
                                                   int* __restrict__ cur,
                                                   float* __restrict__ dinv,
                                                   int n, int nb) {
    __shared__ int wsum[8];
    __shared__ int porig[64];
    __shared__ int pincl[64];
    int tid  = threadIdx.x;
    int lane = tid & 31, wid = tid >> 5;

    if (tid < 64) {
        int v = (tid < nb) ? part[tid] : 0;
        porig[tid] = v;
        int x = v;
#pragma unroll
        for (int o = 1; o < 32; o <<= 1) {
            int u = __shfl_up_sync(0xffffffffu, x, o);
            if (lane >= o) x += u;
        }
        pincl[tid] = x;
    }
    __syncthreads();
    int bi = blockIdx.x;
    int bincl = pincl[bi] + ((bi >= 32) ? pincl[31] : 0);
    int bexc  = bincl - porig[bi];
    if (bi == nb - 1 && tid == 0) rowptr[n] = bincl;

    int base = bi * 1024 + tid * 4;

    int4 c = make_int4(0, 0, 0, 0);
    if (base + 3 < n) c = *(const int4*)(cnt + base);
    else {
        int* cp = (int*)&c;
        for (int j = 0; j < 4; j++) cp[j] = (base + j < n) ? cnt[base + j] : 0;
    }
    int s0 = c.x, s1 = s0 + c.y, s2 = s1 + c.z, s3 = s2 + c.w;
    int ts = s3, sc = ts;
#pragma unroll
    for (int o = 1; o < 32; o <<= 1) {
        int u = __shfl_up_sync(0xffffffffu, sc, o);
        if (lane >= o) sc += u;
    }
    if (lane == 31) wsum[wid] = sc;
    __syncthreads();
    if (wid == 0) {
        int w = (lane < 8) ? wsum[lane] : 0;
#pragma unroll
        for (int o = 1; o < 8; o <<= 1) {
            int u = __shfl_up_sync(0xffffffffu, w, o);
            if (lane >= o) w += u;
        }
        if (lane < 8) wsum[lane] = w;
    }
    __syncthreads();

    int off = bexc + (wid ? wsum[wid - 1] : 0) + (sc - ts);
    if (base + 3 < n) {
        int4 r = make_int4(off, off + s0, off + s1, off + s2);
        *(int4*)(rowptr + base) = r;
        *(int4*)(cur + base)    = r;
        float4 dv = make_float4(rsqrtf((float)(c.x + 1)), rsqrtf((float)(c.y + 1)),
                                rsqrtf((float)(c.z + 1)), rsqrtf((float)(c.w + 1)));
        *(float4*)(dinv + base) = dv;
    } else {
        int rr[4] = {off, off + s0, off + s1, off + s2};
        int* cp = (int*)&c;
        for (int j = 0; j < 4; j++)
            if (base + j < n) {
                rowptr[base + j] = rr[j];
                cur[base + j]    = rr[j];
                dinv[base + j]   = rsqrtf((float)(cp[j] + 1));
            }
    }
}

// ---------------------------------------------------------------------------
// CSR fill (8 edges per thread for MLP on the atomic chains)
// ---------------------------------------------------------------------------
__global__ void k_fill(const int* __restrict__ src, const int* __restrict__ dst,
                       int* __restrict__ cur, int* __restrict__ col, int E) {
    int i = (blockIdx.x * blockDim.x + threadIdx.x) * 8;
    if (i + 7 < E) {
        int4 s0 = *(const int4*)(src + i);
        int4 s1 = *(const int4*)(src + i + 4);
        int4 d0 = *(const int4*)(dst + i);
        int4 d1 = *(const int4*)(dst + i + 4);
        int p0 = atomicAdd(&cur[d0.x], 1);
        int p1 = atomicAdd(&cur[d0.y], 1);
        int p2 = atomicAdd(&cur[d0.z], 1);
        int p3 = atomicAdd(&cur[d0.w], 1);
        int p4 = atomicAdd(&cur[d1.x], 1);
        int p5 = atomicAdd(&cur[d1.y], 1);
        int p6 = atomicAdd(&cur[d1.z], 1);
        int p7 = atomicAdd(&cur[d1.w], 1);
        col[p0] = s0.x; col[p1] = s0.y; col[p2] = s0.z; col[p3] = s0.w;
        col[p4] = s1.x; col[p5] = s1.y; col[p6] = s1.z; col[p7] = s1.w;
    } else {
        for (int j = 0; j < 8; j++)
            if (i + j < E) col[atomicAdd(&cur[dst[i + j]], 1)] = src[i + j];
    }
}

// ---------------------------------------------------------------------------
// Tensor-core GEMM via mma.sync (split bf16, fp32 accum), fp16 output:
//   Ch[r,:] = (half) dinv[r] * (A[r,:] @ W)
// ---------------------------------------------------------------------------
static const uint32_t GEMM_SMEM = 65536;

__global__ void __launch_bounds__(256)
k_gemm_mma(const float* __restrict__ A, const uint8_t* __restrict__ wb,
           const float* __restrict__ dinv, __half* __restrict__ Ch, int n) {
    extern __shared__ char sm[];
    uint32_t sbase = smem_u32(sm);
    int tid  = threadIdx.x;
    int wid  = tid >> 5, lane = tid & 31;
    int row0 = blockIdx.x * 128;

    int mrow0 = (wid & 3) * 32;
    int ncol0 = (wid >> 2) * 64;

    float acc[2][8][4];
#pragma unroll
    for (int i = 0; i < 2; i++)
#pragma unroll
        for (int j = 0; j < 8; j++)
#pragma unroll
            for (int q = 0; q < 4; q++) acc[i][j][q] = 0.0f;

    const float4* A4 = (const float4*)A;

    for (int kh = 0; kh < 2; kh++) {
        const float4* wb4 = (const float4*)(wb + kh * 32768);
#pragma unroll
        for (int t = 0; t < 8; t++) {
            int i = tid + t * 256;
            *(float4*)(sm + 32768 + i * 16) = wb4[i];
        }
#pragma unroll
        for (int t = 0; t < 8; t++) {
            int i  = tid + t * 256;
            int m  = i >> 4;
            int f4 = i & 15;
            int gr = row0 + m;
            float4 v = (gr < n) ? A4[(size_t)gr * 32 + kh * 16 + f4]
                                : make_float4(0.f, 0.f, 0.f, 0.f);
            __nv_bfloat16 hx = __float2bfloat16(v.x);
            __nv_bfloat16 hy = __float2bfloat16(v.y);
            __nv_bfloat16 hz = __float2bfloat16(v.z);
            __nv_bfloat16 hw = __float2bfloat16(v.w);
            __nv_bfloat162 h0, h1, l0, l1;
            h0.x = hx; h0.y = hy; h1.x = hz; h1.y = hw;
            l0.x = __float2bfloat16(v.x - __bfloat162float(hx));
            l0.y = __float2bfloat16(v.y - __bfloat162float(hy));
            l1.x = __float2bfloat16(v.z - __bfloat162float(hz));
            l1.y = __float2bfloat16(v.w - __bfloat162float(hw));
            uint32_t off = swz128((uint32_t)(m * 128 + f4 * 8));
            *(__nv_bfloat162*)(sm + off)             = h0;
            *(__nv_bfloat162*)(sm + off + 4)         = h1;
            *(__nv_bfloat162*)(sm + 16384 + off)     = l0;
            *(__nv_bfloat162*)(sm + 16384 + off + 4) = l1;
        }
        __syncthreads();

#pragma unroll
        for (int k16 = 0; k16 < 4; k16++) {
            int kbyte = k16 * 32;
            uint32_t afh[2][4], afl[2][4];
#pragma unroll
            for (int mt = 0; mt < 2; mt++) {
                int mrow = mrow0 + mt * 16 + (lane & 7) + ((lane & 8) ? 8 : 0);
                int kb   = kbyte + ((lane & 16) ? 16 : 0);
                uint32_t a = sbase + swz128((uint32_t)(mrow * 128 + kb));
                ldsm_x4(afh[mt][0], afh[mt][1], afh[mt][2], afh[mt][3], a);
                ldsm_x4(afl[mt][0], afl[mt][1], afl[mt][2], afl[mt][3], a + 16384);
            }
#pragma unroll
            for (int nt = 0; nt < 8; nt++) {
                int nrow = ncol0 + nt * 8 + (lane & 7);
                int kb   = kbyte + ((lane & 8) ? 16 : 0);
                uint32_t baddr = sbase + 32768 + swz128((uint32_t)(nrow * 128 + kb));
                uint32_t bh0, bh1, bl0, bl1;
                ldsm_x2(bh0, bh1, baddr);
                ldsm_x2(bl0, bl1, baddr + 16384);
#pragma unroll
                for (int mt = 0; mt < 2; mt++) {
                    mma_bf16(acc[mt][nt][0], acc[mt][nt][1], acc[mt][nt][2], acc[mt][nt][3],
                             afh[mt][0], afh[mt][1], afh[mt][2], afh[mt][3], bh0, bh1);
                    mma_bf16(acc[mt][nt][0], acc[mt][nt][1], acc[mt][nt][2], acc[mt][nt][3],
                             afh[mt][0], afh[mt][1], afh[mt][2], afh[mt][3], bl0, bl1);
                    mma_bf16(acc[mt][nt][0], acc[mt][nt][1], acc[mt][nt][2], acc[mt][nt][3],
                             afl[mt][0], afl[mt][1], afl[mt][2], afl[mt][3], bh0, bh1);
                }
            }
        }
        __syncthreads();
    }

#pragma unroll
    for (int mt = 0; mt < 2; mt++) {
        int r1 = row0 + mrow0 + mt * 16 + (lane >> 2);
        int r2 = r1 + 8;
        float s1 = (r1 < n) ? dinv[r1] : 0.f;
        float s2 = (r2 < n) ? dinv[r2] : 0.f;
#pragma unroll
        for (int nt = 0; nt < 8; nt++) {
            int col = ncol0 + nt * 8 + ((lane & 3) << 1);
            if (r1 < n)
                *(__half2*)(Ch + (size_t)r1 * DD + col) =
                    __floats2half2_rn(acc[mt][nt][0] * s1, acc[mt][nt][1] * s1);
            if (r2 < n)
                *(__half2*)(Ch + (size_t)r2 * DD + col) =
                    __floats2half2_rn(acc[mt][nt][2] * s2, acc[mt][nt][3] * s2);
        }
    }
}

// ---------------------------------------------------------------------------
// Fused CSR gather + self-loop + bias + ELU.
// FOUR nodes per warp: 8-lane groups. Group q -> node 4w+q. Lane ql owns
// 2 x uint4 (16 halves = cols ql*16..ql*16+16). 2 LDG.128 per edge per lane.
// Groups iterate independently (split masks, shfl width 8).
// ---------------------------------------------------------------------------
__device__ __forceinline__ float eluf(float x) { return x > 0.0f ? x : expm1f(x); }

__device__ __forceinline__ void acc_h8(float4& a0, float4& a1, uint4 u) {
    float2 f0 = __half22float2(*(const __half2*)&u.x);
    float2 f1 = __half22float2(*(const __half2*)&u.y);
    float2 f2 = __half22float2(*(const __half2*)&u.z);
    float2 f3 = __half22float2(*(const __half2*)&u.w);
    a0.x += f0.x; a0.y += f0.y; a0.z += f1.x; a0.w += f1.y;
    a1.x += f2.x; a1.y += f2.y; a1.z += f3.x; a1.w += f3.y;
}

__global__ __launch_bounds__(256) void k_gather(const __half* __restrict__ hp,
                                                const int* __restrict__ rowptr,
                                                const int* __restrict__ colv,
                                                const float* __restrict__ dinv,
                                                const float* __restrict__ b,
                                                float* __restrict__ outp, int n) {
    int lane = threadIdx.x & 31;
    int q    = lane >> 3;          // group 0..3
    int ql   = lane & 7;           // lane within group
    int d    = (blockIdx.x * 8 + (threadIdx.x >> 5)) * 4 + q;
    uint32_t gmask = 0xFFu << (q * 8);

    bool valid = d < n;
    int dd     = valid ? d : 0;

    const uint4* hp4 = (const uint4*)hp;   // 16 uint4 (8 halves each) per row

    int start = rowptr[dd];
    int end   = valid ? rowptr[dd + 1] : start;

    float4 a0 = make_float4(0.f, 0.f, 0.f, 0.f);
    float4 a1 = make_float4(0.f, 0.f, 0.f, 0.f);
    float4 a2 = make_float4(0.f, 0.f, 0.f, 0.f);
    float4 a3 = make_float4(0.f, 0.f, 0.f, 0.f);
    {
        uint4 u0 = hp4[(size_t)dd * 16 + ql * 2];
        uint4 u1 = hp4[(size_t)dd * 16 + ql * 2 + 1];
        acc_h8(a0, a1, u0);
        acc_h8(a2, a3, u1);
    }

    for (int base = start; base < end; base += 8) {
        int cnt  = min(8, end - base);
        int sidx = (base + ql < end) ? colv[base + ql] : 0;
        int j = 0;
        for (; j + 2 <= cnt; j += 2) {
            int s0 = __shfl_sync(gmask, sidx, j,     8);
            int s1 = __shfl_sync(gmask, sidx, j + 1, 8);
            uint4 u00 = hp4[(size_t)s0 * 16 + ql * 2];
            uint4 u01 = hp4[(size_t)s0 * 16 + ql * 2 + 1];
            uint4 u10 = hp4[(size_t)s1 * 16 + ql * 2];
            uint4 u11 = hp4[(size_t)s1 * 16 + ql * 2 + 1];
            acc_h8(a0, a1, u00);
            acc_h8(a2, a3, u01);
            acc_h8(a0, a1, u10);
            acc_h8(a2, a3, u11);
        }
        for (; j < cnt; j++) {
            int s = __shfl_sync(gmask, sidx, j, 8);
            uint4 u0 = hp4[(size_t)s * 16 + ql * 2];
            uint4 u1 = hp4[(size_t)s * 16 + ql * 2 + 1];
            acc_h8(a0, a1, u0);
            acc_h8(a2, a3, u1);
        }
    }

    if (valid) {
        float w = dinv[dd];
        // lane owns cols [ql*16, ql*16+16)
        float4 b0 = ((const float4*)b)[ql * 4];
        float4 b1 = ((const float4*)b)[ql * 4 + 1];
        float4 b2 = ((const float4*)b)[ql * 4 + 2];
        float4 b3 = ((const float4*)b)[ql * 4 + 3];
        a0.x = eluf(a0.x * w + b0.x); a0.y = eluf(a0.y * w + b0.y);
        a0.z = eluf(a0.z * w + b0.z); a0.w = eluf(a0.w * w + b0.w);
        a1.x = eluf(a1.x * w + b1.x); a1.y = eluf(a1.y * w + b1.y);
        a1.z = eluf(a1.z * w + b1.z); a1.w = eluf(a1.w * w + b1.w);
        a2.x = eluf(a2.x * w + b2.x); a2.y = eluf(a2.y * w + b2.y);
        a2.z = eluf(a2.z * w + b2.z); a2.w = eluf(a2.w * w + b2.w);
        a3.x = eluf(a3.x * w + b3.x); a3.y = eluf(a3.y * w + b3.y);
        a3.z = eluf(a3.z * w + b3.z); a3.w = eluf(a3.w * w + b3.w);
        float4* op = (float4*)outp + (size_t)dd * 32 + ql * 4;
        op[0] = a0; op[1] = a1; op[2] = a2; op[3] = a3;
    }
}

// ---------------------------------------------------------------------------
// Launch
// ---------------------------------------------------------------------------
extern "C" void kernel_launch(void* const* d_in, const int* in_sizes, int n_in,
                              void* d_out, int out_size) {
    const float* x  = (const float*)d_in[0];
    const int*   ei = (const int*)d_in[1];
    const float* W1 = (const float*)d_in[2];
    const float* b1 = (const float*)d_in[3];
    const float* W2 = (const float*)d_in[4];
    const float* b2 = (const float*)d_in[5];
    float* out = (float*)d_out;

    int N = in_sizes[0] / DD;
    int E = in_sizes[1] / 2;
    const int* src = ei;
    const int* dst = ei + E;

    float *dinv, *buf2;
    __half* hbuf;
    int *cnt, *rowptr, *cur, *col, *part;
    uint8_t *wb1, *wb2;
    cudaGetSymbolAddress((void**)&dinv, g_dinv);
    cudaGetSymbolAddress((void**)&hbuf, g_hbuf);
    cudaGetSymbolAddress((void**)&buf2, g_buf2);
    cudaGetSymbolAddress((void**)&cnt, g_cnt);
    cudaGetSymbolAddress((void**)&rowptr, g_rowptr);
    cudaGetSymbolAddress((void**)&cur, g_cur);
    cudaGetSymbolAddress((void**)&col, g_col);
    cudaGetSymbolAddress((void**)&part, g_part);
    cudaGetSymbolAddress((void**)&wb1, g_wb1);
    cudaGetSymbolAddress((void**)&wb2, g_wb2);

    cudaFuncSetAttribute(k_gemm_mma, cudaFuncAttributeMaxDynamicSharedMemorySize,
                         GEMM_SMEM);

    const int T  = 256;
    int nb       = (N + 1023) / 1024;          // <= 64 partials
    int egrid8   = (E / 8 + T - 1) / T;        // 8 edges/thread kernels

    // CSR build + normalization (+ fused W prep)
    cudaMemsetAsync(cnt, 0, (size_t)N * sizeof(int));
    k_hist_wprep<<<egrid8 + 128, T>>>(dst, cnt, E, egrid8, W1, wb1, W2, wb2);
    k_scan_partial<<<nb, T>>>(cnt, part, N);
    k_scan_down<<<nb, T>>>(cnt, part, rowptr, cur, dinv, N, nb);
    k_fill<<<egrid8, T>>>(src, dst, cur, col, E);

    int gemm_grid   = (N + 127) / 128;
    int gather_grid = (N + 31) / 32;   // 8 warps/block, 4 nodes/warp

    // Layer 1
    k_gemm_mma<<<gemm_grid, 256, GEMM_SMEM>>>(x, wb1, dinv, hbuf, N);
    k_gather<<<gather_grid, 256>>>(hbuf, rowptr, col, dinv, b1, buf2, N);

    // Layer 2
    k_gemm_mma<<<gemm_grid, 256, GEMM_SMEM>>>(buf2, wb2, dinv, hbuf, N);
    k_gather<<<gather_grid, 256>>>(hbuf, rowptr, col, dinv, b2, out, N);
}

// round 11
// speedup vs baseline: 1.0018x; 1.0018x over previous
#include <cuda_runtime.h>
#include <cuda_bf16.h>
#include <cuda_fp16.h>
#include <math.h>
#include <stdint.h>

#define DD   128
#define MAXN 50000
#define MAXE 800000

// Scratch (allocation-free rule: __device__ globals)
__device__ __align__(16) float   g_dinv[MAXN];
__device__ __align__(16) __half  g_hbuf[(size_t)MAXN * DD];  // fp16 messages
__device__ __align__(16) float   g_buf2[(size_t)MAXN * DD];  // fp32 activation
__device__ __align__(16) int     g_cnt[MAXN];
__device__ __align__(16) int     g_rowptr[MAXN + 4];
__device__ __align__(16) int     g_cur[MAXN];
__device__ __align__(16) int     g_col[MAXE];
__device__ __align__(16) int     g_part[64];
// Pre-split/transposed/swizzled W images (one per layer):
// [kh0: Bhi 16KB | Blo 16KB][kh1: Bhi 16KB | Blo 16KB]  (Bt[n][k] bf16, SW128)
__device__ __align__(16) uint8_t g_wb1[65536];
__device__ __align__(16) uint8_t g_wb2[65536];

// ---------------------------------------------------------------------------
// Helpers (sm_80+ only: ldmatrix + mma.sync — NO tcgen05, target is sm_103)
// ---------------------------------------------------------------------------
__device__ __forceinline__ uint32_t swz128(uint32_t off) {
    return off ^ ((off >> 3) & 0x70);
}
__device__ __forceinline__ uint32_t smem_u32(const void* p) {
    return (uint32_t)__cvta_generic_to_shared(p);
}

__device__ __forceinline__ void ldsm_x4(uint32_t& r0, uint32_t& r1,
                                        uint32_t& r2, uint32_t& r3, uint32_t addr) {
    asm volatile("ldmatrix.sync.aligned.m8n8.x4.shared.b16 {%0,%1,%2,%3}, [%4];"
                 : "=r"(r0), "=r"(r1), "=r"(r2), "=r"(r3) : "r"(addr));
}
__device__ __forceinline__ void ldsm_x2(uint32_t& r0, uint32_t& r1, uint32_t addr) {
    asm volatile("ldmatrix.sync.aligned.m8n8.x2.shared.b16 {%0,%1}, [%2];"
                 : "=r"(r0), "=r"(r1) : "r"(addr));
}
__device__ __forceinline__ void mma_bf16(float& d0, float& d1, float& d2, float& d3,
                                         uint32_t a0, uint32_t a1, uint32_t a2, uint32_t a3,
                                         uint32_t b0, uint32_t b1) {
    asm volatile(
        "mma.sync.aligned.m16n8k16.row.col.f32.bf16.bf16.f32 "
        "{%0,%1,%2,%3}, {%4,%5,%6,%7}, {%8,%9}, {%0,%1,%2,%3};"
        : "+f"(d0), "+f"(d1), "+f"(d2), "+f"(d3)
        : "r"(a0), "r"(a1), "r"(a2), "r"(a3), "r"(b0), "r"(b1));
}

// ---------------------------------------------------------------------------
// W split helper (shared by the fused hist+wprep kernel)
// ---------------------------------------------------------------------------
__device__ __forceinline__ void wprep_one(const float* __restrict__ W,
                                          uint8_t* __restrict__ wb, int idx) {
    int nn = idx & 127;           // output col -> Bt row
    int k  = idx >> 7;            // input dim  -> Bt col
    float v = W[k * DD + nn];
    __nv_bfloat16 hi = __float2bfloat16(v);
    __nv_bfloat16 lo = __float2bfloat16(v - __bfloat162float(hi));
    int half = k >> 6, kk = k & 63;
    uint32_t off = swz128((uint32_t)(nn * 128 + kk * 2));
    *(__nv_bfloat16*)(wb + half * 32768 + off)         = hi;
    *(__nv_bfloat16*)(wb + half * 32768 + 16384 + off) = lo;
}

// ---------------------------------------------------------------------------
// Fused: histogram of dst (blocks < eb, 8 edges/thread) + W1/W2 prep
// ---------------------------------------------------------------------------
__global__ void k_hist_wprep(const int* __restrict__ dst, int* __restrict__ cnt,
                             int E, int eb,
                             const float* __restrict__ W1, uint8_t* __restrict__ wb1,
                             const float* __restrict__ W2, uint8_t* __restrict__ wb2) {
    int b = blockIdx.x;
    if (b < eb) {
        int i = (b * blockDim.x + threadIdx.x) * 8;
        if (i + 7 < E) {
            int4 d0 = *(const int4*)(dst + i);
            int4 d1 = *(const int4*)(dst + i + 4);
            atomicAdd(&cnt[d0.x], 1);
            atomicAdd(&cnt[d0.y], 1);
            atomicAdd(&cnt[d0.z], 1);
            atomicAdd(&cnt[d0.w], 1);
            atomicAdd(&cnt[d1.x], 1);
            atomicAdd(&cnt[d1.y], 1);
            atomicAdd(&cnt[d1.z], 1);
            atomicAdd(&cnt[d1.w], 1);
        } else {
            for (int j = 0; j < 8; j++)
                if (i + j < E) atomicAdd(&cnt[dst[i + j]], 1);
        }
    } else if (b < eb + 64) {
        wprep_one(W1, wb1, (b - eb) * 256 + threadIdx.x);
    } else {
        wprep_one(W2, wb2, (b - eb - 64) * 256 + threadIdx.x);
    }
}

// ---------------------------------------------------------------------------
// 2-phase exclusive scan (+ dinv epilogue). Phase 1: per-block (1024) sums.
// ---------------------------------------------------------------------------
__global__ __launch_bounds__(256) void k_scan_partial(const int* __restrict__ cnt,
                                                      int* __restrict__ part, int n) {
    __shared__ int sh[8];
    int tid  = threadIdx.x;
    int base = blockIdx.x * 1024 + tid * 4;
    int s = 0;
    if (base + 3 < n) {
        int4 v = *(const int4*)(cnt + base);
        s = v.x + v.y + v.z + v.w;
    } else {
        for (int j = 0; j < 4; j++)
            if (base + j < n) s += cnt[base + j];
    }
#pragma unroll
    for (int o = 16; o; o >>= 1) s += __shfl_down_sync(0xffffffffu, s, o);
    if ((tid & 31) == 0) sh[tid >> 5] = s;
    __syncthreads();
    if (tid < 8) {
        s = sh[tid];
#pragma unroll
        for (int o = 4; o; o >>= 1) s += __shfl_down_sync(0x000000ffu, s, o);
        if (tid == 0) part[blockIdx.x] = s;
    }
}

// Phase 2 (fused tops-scan): every block redundantly scans the <=64 partials
// in-register, takes its own exclusive offset, then does the downsweep.
__global__ __launch_bounds__(256) void k_scan_down(const int* __restrict__ cnt,
                                                   const int* __restrict__ part,
                                                   int* __restrict__ rowptr,
                                                   int* __restrict__ cur,
                                                   float* __restrict__ dinv,
                                                   int n, int nb) {
    __shared__ int wsum[8];
    __shared__ int porig[64];
    __shared__ int pincl[64];
    int tid  = threadIdx.x;
    int lane = tid & 31, wid = tid >> 5;

    if (tid < 64) {
        int v = (tid < nb) ? part[tid] : 0;
        porig[tid] = v;
        int x = v;
#pragma unroll
        for (int o = 1; o < 32; o <<= 1) {
            int u = __shfl_up_sync(0xffffffffu, x, o);
            if (lane >= o) x += u;
        }
        pincl[tid] = x;
    }
    __syncthreads();
    int bi = blockIdx.x;
    int bincl = pincl[bi] + ((bi >= 32) ? pincl[31] : 0);
    int bexc  = bincl - porig[bi];
    if (bi == nb - 1 && tid == 0) rowptr[n] = bincl;

    int base = bi * 1024 + tid * 4;

    int4 c = make_int4(0, 0, 0, 0);
    if (base + 3 < n) c = *(const int4*)(cnt + base);
    else {
        int* cp = (int*)&c;
        for (int j = 0; j < 4; j++) cp[j] = (base + j < n) ? cnt[base + j] : 0;
    }
    int s0 = c.x, s1 = s0 + c.y, s2 = s1 + c.z, s3 = s2 + c.w;
    int ts = s3, sc = ts;
#pragma unroll
    for (int o = 1; o < 32; o <<= 1) {
        int u = __shfl_up_sync(0xffffffffu, sc, o);
        if (lane >= o) sc += u;
    }
    if (lane == 31) wsum[wid] = sc;
    __syncthreads();
    if (wid == 0) {
        int w = (lane < 8) ? wsum[lane] : 0;
#pragma unroll
        for (int o = 1; o < 8; o <<= 1) {
            int u = __shfl_up_sync(0xffffffffu, w, o);
            if (lane >= o) w += u;
        }
        if (lane < 8) wsum[lane] = w;
    }
    __syncthreads();

    int off = bexc + (wid ? wsum[wid - 1] : 0) + (sc - ts);
    if (base + 3 < n) {
        int4 r = make_int4(off, off + s0, off + s1, off + s2);
        *(int4*)(rowptr + base) = r;
        *(int4*)(cur + base)    = r;
        float4 dv = make_float4(rsqrtf((float)(c.x + 1)), rsqrtf((float)(c.y + 1)),
                                rsqrtf((float)(c.z + 1)), rsqrtf((float)(c.w + 1)));
        *(float4*)(dinv + base) = dv;
    } else {
        int rr[4] = {off, off + s0, off + s1, off + s2};
        int* cp = (int*)&c;
        for (int j = 0; j < 4; j++)
            if (base + j < n) {
                rowptr[base + j] = rr[j];
                cur[base + j]    = rr[j];
                dinv[base + j]   = rsqrtf((float)(cp[j] + 1));
            }
    }
}

// ---------------------------------------------------------------------------
// CSR fill (8 edges per thread for MLP on the atomic chains)
// ---------------------------------------------------------------------------
__global__ void k_fill(const int* __restrict__ src, const int* __restrict__ dst,
                       int* __restrict__ cur, int* __restrict__ col, int E) {
    int i = (blockIdx.x * blockDim.x + threadIdx.x) * 8;
    if (i + 7 < E) {
        int4 s0 = *(const int4*)(src + i);
        int4 s1 = *(const int4*)(src + i + 4);
        int4 d0 = *(const int4*)(dst + i);
        int4 d1 = *(const int4*)(dst + i + 4);
        int p0 = atomicAdd(&cur[d0.x], 1);
        int p1 = atomicAdd(&cur[d0.y], 1);
        int p2 = atomicAdd(&cur[d0.z], 1);
        int p3 = atomicAdd(&cur[d0.w], 1);
        int p4 = atomicAdd(&cur[d1.x], 1);
        int p5 = atomicAdd(&cur[d1.y], 1);
        int p6 = atomicAdd(&cur[d1.z], 1);
        int p7 = atomicAdd(&cur[d1.w], 1);
        col[p0] = s0.x; col[p1] = s0.y; col[p2] = s0.z; col[p3] = s0.w;
        col[p4] = s1.x; col[p5] = s1.y; col[p6] = s1.z; col[p7] = s1.w;
    } else {
        for (int j = 0; j < 8; j++)
            if (i + j < E) col[atomicAdd(&cur[dst[i + j]], 1)] = src[i + j];
    }
}

// ---------------------------------------------------------------------------
// Tensor-core GEMM via mma.sync (split bf16, fp32 accum), fp16 output:
//   Ch[r,:] = (half) dinv[r] * (A[r,:] @ W)
// ---------------------------------------------------------------------------
static const uint32_t GEMM_SMEM = 65536;

__global__ void __launch_bounds__(256)
k_gemm_mma(const float* __restrict__ A, const uint8_t* __restrict__ wb,
           const float* __restrict__ dinv, __half* __restrict__ Ch, int n) {
    extern __shared__ char sm[];
    uint32_t sbase = smem_u32(sm);
    int tid  = threadIdx.x;
    int wid  = tid >> 5, lane = tid & 31;
    int row0 = blockIdx.x * 128;

    int mrow0 = (wid & 3) * 32;
    int ncol0 = (wid >> 2) * 64;

    float acc[2][8][4];
#pragma unroll
    for (int i = 0; i < 2; i++)
#pragma unroll
        for (int j = 0; j < 8; j++)
#pragma unroll
            for (int q = 0; q < 4; q++) acc[i][j][q] = 0.0f;

    const float4* A4 = (const float4*)A;

    for (int kh = 0; kh < 2; kh++) {
        const float4* wb4 = (const float4*)(wb + kh * 32768);
#pragma unroll
        for (int t = 0; t < 8; t++) {
            int i = tid + t * 256;
            *(float4*)(sm + 32768 + i * 16) = wb4[i];
        }
#pragma unroll
        for (int t = 0; t < 8; t++) {
            int i  = tid + t * 256;
            int m  = i >> 4;
            int f4 = i & 15;
            int gr = row0 + m;
            float4 v = (gr < n) ? A4[(size_t)gr * 32 + kh * 16 + f4]
                                : make_float4(0.f, 0.f, 0.f, 0.f);
            __nv_bfloat16 hx = __float2bfloat16(v.x);
            __nv_bfloat16 hy = __float2bfloat16(v.y);
            __nv_bfloat16 hz = __float2bfloat16(v.z);
            __nv_bfloat16 hw = __float2bfloat16(v.w);
            __nv_bfloat162 h0, h1, l0, l1;
            h0.x = hx; h0.y = hy; h1.x = hz; h1.y = hw;
            l0.x = __float2bfloat16(v.x - __bfloat162float(hx));
            l0.y = __float2bfloat16(v.y - __bfloat162float(hy));
            l1.x = __float2bfloat16(v.z - __bfloat162float(hz));
            l1.y = __float2bfloat16(v.w - __bfloat162float(hw));
            uint32_t off = swz128((uint32_t)(m * 128 + f4 * 8));
            *(__nv_bfloat162*)(sm + off)             = h0;
            *(__nv_bfloat162*)(sm + off + 4)         = h1;
            *(__nv_bfloat162*)(sm + 16384 + off)     = l0;
            *(__nv_bfloat162*)(sm + 16384 + off + 4) = l1;
        }
        __syncthreads();

#pragma unroll
        for (int k16 = 0; k16 < 4; k16++) {
            int kbyte = k16 * 32;
            uint32_t afh[2][4], afl[2][4];
#pragma unroll
            for (int mt = 0; mt < 2; mt++) {
                int mrow = mrow0 + mt * 16 + (lane & 7) + ((lane & 8) ? 8 : 0);
                int kb   = kbyte + ((lane & 16) ? 16 : 0);
                uint32_t a = sbase + swz128((uint32_t)(mrow * 128 + kb));
                ldsm_x4(afh[mt][0], afh[mt][1], afh[mt][2], afh[mt][3], a);
                ldsm_x4(afl[mt][0], afl[mt][1], afl[mt][2], afl[mt][3], a + 16384);
            }
#pragma unroll
            for (int nt = 0; nt < 8; nt++) {
                int nrow = ncol0 + nt * 8 + (lane & 7);
                int kb   = kbyte + ((lane & 8) ? 16 : 0);
                uint32_t baddr = sbase + 32768 + swz128((uint32_t)(nrow * 128 + kb));
                uint32_t bh0, bh1, bl0, bl1;
                ldsm_x2(bh0, bh1, baddr);
                ldsm_x2(bl0, bl1, baddr + 16384);
#pragma unroll
                for (int mt = 0; mt < 2; mt++) {
                    mma_bf16(acc[mt][nt][0], acc[mt][nt][1], acc[mt][nt][2], acc[mt][nt][3],
                             afh[mt][0], afh[mt][1], afh[mt][2], afh[mt][3], bh0, bh1);
                    mma_bf16(acc[mt][nt][0], acc[mt][nt][1], acc[mt][nt][2], acc[mt][nt][3],
                             afh[mt][0], afh[mt][1], afh[mt][2], afh[mt][3], bl0, bl1);
                    mma_bf16(acc[mt][nt][0], acc[mt][nt][1], acc[mt][nt][2], acc[mt][nt][3],
                             afl[mt][0], afl[mt][1], afl[mt][2], afl[mt][3], bh0, bh1);
                }
            }
        }
        __syncthreads();
    }

#pragma unroll
    for (int mt = 0; mt < 2; mt++) {
        int r1 = row0 + mrow0 + mt * 16 + (lane >> 2);
        int r2 = r1 + 8;
        float s1 = (r1 < n) ? dinv[r1] : 0.f;
        float s2 = (r2 < n) ? dinv[r2] : 0.f;
#pragma unroll
        for (int nt = 0; nt < 8; nt++) {
            int col = ncol0 + nt * 8 + ((lane & 3) << 1);
            if (r1 < n)
                *(__half2*)(Ch + (size_t)r1 * DD + col) =
                    __floats2half2_rn(acc[mt][nt][0] * s1, acc[mt][nt][1] * s1);
            if (r2 < n)
                *(__half2*)(Ch + (size_t)r2 * DD + col) =
                    __floats2half2_rn(acc[mt][nt][2] * s2, acc[mt][nt][3] * s2);
        }
    }
}

// ---------------------------------------------------------------------------
// Fused CSR gather + self-loop + bias + ELU.
// FOUR nodes per warp: 8-lane groups. Group q -> node 4w+q. Lane ql owns
// 2 x uint4 (16 halves = cols ql*16..ql*16+16). 2 LDG.128 per edge per lane.
// Groups iterate independently (split masks, shfl width 8).
// ---------------------------------------------------------------------------
__device__ __forceinline__ float eluf(float x) { return x > 0.0f ? x : expm1f(x); }

__device__ __forceinline__ void acc_h8(float4& a0, float4& a1, uint4 u) {
    float2 f0 = __half22float2(*(const __half2*)&u.x);
    float2 f1 = __half22float2(*(const __half2*)&u.y);
    float2 f2 = __half22float2(*(const __half2*)&u.z);
    float2 f3 = __half22float2(*(const __half2*)&u.w);
    a0.x += f0.x; a0.y += f0.y; a0.z += f1.x; a0.w += f1.y;
    a1.x += f2.x; a1.y += f2.y; a1.z += f3.x; a1.w += f3.y;
}

__global__ __launch_bounds__(256) void k_gather(const __half* __restrict__ hp,
                                                const int* __restrict__ rowptr,
                                                const int* __restrict__ colv,
                                                const float* __restrict__ dinv,
                                                const float* __restrict__ b,
                                                float* __restrict__ outp, int n) {
    int lane = threadIdx.x & 31;
    int q    = lane >> 3;          // group 0..3
    int ql   = lane & 7;           // lane within group
    int d    = (blockIdx.x * 8 + (threadIdx.x >> 5)) * 4 + q;
    uint32_t gmask = 0xFFu << (q * 8);

    bool valid = d < n;
    int dd     = valid ? d : 0;

    const uint4* hp4 = (const uint4*)hp;   // 16 uint4 (8 halves each) per row

    int start = rowptr[dd];
    int end   = valid ? rowptr[dd + 1] : start;

    float4 a0 = make_float4(0.f, 0.f, 0.f, 0.f);
    float4 a1 = make_float4(0.f, 0.f, 0.f, 0.f);
    float4 a2 = make_float4(0.f, 0.f, 0.f, 0.f);
    float4 a3 = make_float4(0.f, 0.f, 0.f, 0.f);
    {
        uint4 u0 = hp4[(size_t)dd * 16 + ql * 2];
        uint4 u1 = hp4[(size_t)dd * 16 + ql * 2 + 1];
        acc_h8(a0, a1, u0);
        acc_h8(a2, a3, u1);
    }

    for (int base = start; base < end; base += 8) {
        int cnt  = min(8, end - base);
        int sidx = (base + ql < end) ? colv[base + ql] : 0;
        int j = 0;
        for (; j + 2 <= cnt; j += 2) {
            int s0 = __shfl_sync(gmask, sidx, j,     8);
            int s1 = __shfl_sync(gmask, sidx, j + 1, 8);
            uint4 u00 = hp4[(size_t)s0 * 16 + ql * 2];
            uint4 u01 = hp4[(size_t)s0 * 16 + ql * 2 + 1];
            uint4 u10 = hp4[(size_t)s1 * 16 + ql * 2];
            uint4 u11 = hp4[(size_t)s1 * 16 + ql * 2 + 1];
            acc_h8(a0, a1, u00);
            acc_h8(a2, a3, u01);
            acc_h8(a0, a1, u10);
            acc_h8(a2, a3, u11);
        }
        for (; j < cnt; j++) {
            int s = __shfl_sync(gmask, sidx, j, 8);
            uint4 u0 = hp4[(size_t)s * 16 + ql * 2];
            uint4 u1 = hp4[(size_t)s * 16 + ql * 2 + 1];
            acc_h8(a0, a1, u0);
            acc_h8(a2, a3, u1);
        }
    }

    if (valid) {
        float w = dinv[dd];
        // lane owns cols [ql*16, ql*16+16)
        float4 b0 = ((const float4*)b)[ql * 4];
        float4 b1 = ((const float4*)b)[ql * 4 + 1];
        float4 b2 = ((const float4*)b)[ql * 4 + 2];
        float4 b3 = ((const float4*)b)[ql * 4 + 3];
        a0.x = eluf(a0.x * w + b0.x); a0.y = eluf(a0.y * w + b0.y);
        a0.z = eluf(a0.z * w + b0.z); a0.w = eluf(a0.w * w + b0.w);
        a1.x = eluf(a1.x * w + b1.x); a1.y = eluf(a1.y * w + b1.y);
        a1.z = eluf(a1.z * w + b1.z); a1.w = eluf(a1.w * w + b1.w);
        a2.x = eluf(a2.x * w + b2.x); a2.y = eluf(a2.y * w + b2.y);
        a2.z = eluf(a2.z * w + b2.z); a2.w = eluf(a2.w * w + b2.w);
        a3.x = eluf(a3.x * w + b3.x); a3.y = eluf(a3.y * w + b3.y);
        a3.z = eluf(a3.z * w + b3.z); a3.w = eluf(a3.w * w + b3.w);
        float4* op = (float4*)outp + (size_t)dd * 32 + ql * 4;
        op[0] = a0; op[1] = a1; op[2] = a2; op[3] = a3;
    }
}

// ---------------------------------------------------------------------------
// Launch
// ---------------------------------------------------------------------------
extern "C" void kernel_launch(void* const* d_in, const int* in_sizes, int n_in,
                              void* d_out, int out_size) {
    const float* x  = (const float*)d_in[0];
    const int*   ei = (const int*)d_in[1];
    const float* W1 = (const float*)d_in[2];
    const float* b1 = (const float*)d_in[3];
    const float* W2 = (const float*)d_in[4];
    const float* b2 = (const float*)d_in[5];
    float* out = (float*)d_out;

    int N = in_sizes[0] / DD;
    int E = in_sizes[1] / 2;
    const int* src = ei;
    const int* dst = ei + E;

    float *dinv, *buf2;
    __half* hbuf;
    int *cnt, *rowptr, *cur, *col, *part;
    uint8_t *wb1, *wb2;
    cudaGetSymbolAddress((void**)&dinv, g_dinv);
    cudaGetSymbolAddress((void**)&hbuf, g_hbuf);
    cudaGetSymbolAddress((void**)&buf2, g_buf2);
    cudaGetSymbolAddress((void**)&cnt, g_cnt);
    cudaGetSymbolAddress((void**)&rowptr, g_rowptr);
    cudaGetSymbolAddress((void**)&cur, g_cur);
    cudaGetSymbolAddress((void**)&col, g_col);
    cudaGetSymbolAddress((void**)&part, g_part);
    cudaGetSymbolAddress((void**)&wb1, g_wb1);
    cudaGetSymbolAddress((void**)&wb2, g_wb2);

    cudaFuncSetAttribute(k_gemm_mma, cudaFuncAttributeMaxDynamicSharedMemorySize,
                         GEMM_SMEM);

    const int T  = 256;
    int nb       = (N + 1023) / 1024;          // <= 64 partials
    int egrid8   = (E / 8 + T - 1) / T;        // 8 edges/thread kernels

    // CSR build + normalization (+ fused W prep)
    cudaMemsetAsync(cnt, 0, (size_t)N * sizeof(int));
    k_hist_wprep<<<egrid8 + 128, T>>>(dst, cnt, E, egrid8, W1, wb1, W2, wb2);
    k_scan_partial<<<nb, T>>>(cnt, part, N);
    k_scan_down<<<nb, T>>>(cnt, part, rowptr, cur, dinv, N, nb);
    k_fill<<<egrid8, T>>>(src, dst, cur, col, E);

    int gemm_grid   = (N + 127) / 128;
    int gather_grid = (N + 31) / 32;   // 8 warps/block, 4 nodes/warp

    // Layer 1
    k_gemm_mma<<<gemm_grid, 256, GEMM_SMEM>>>(x, wb1, dinv, hbuf, N);
    k_gather<<<gather_grid, 256>>>(hbuf, rowptr, col, dinv, b1, buf2, N);

    // Layer 2
    k_gemm_mma<<<gemm_grid, 256, GEMM_SMEM>>>(buf2, wb2, dinv, hbuf, N);
    k_gather<<<gather_grid, 256>>>(hbuf, rowptr, col, dinv, b2, out, N);
}

// round 12
// speedup vs baseline: 1.0625x; 1.0606x over previous
#include <cuda_runtime.h>
#include <cuda_bf16.h>
#include <cuda_fp16.h>
#include <math.h>
#include <stdint.h>

#define DD   128
#define MAXN 50000
#define MAXE 800000

// Scratch (allocation-free rule: __device__ globals)
__device__ __align__(16) float   g_dinv[MAXN];
__device__ __align__(16) __half  g_hbuf[(size_t)MAXN * DD];  // fp16 messages
__device__ __align__(16) float   g_buf2[(size_t)MAXN * DD];  // fp32 activation
__device__ __align__(16) int     g_cnt[MAXN];
__device__ __align__(16) int     g_rowptr[MAXN + 4];
__device__ __align__(16) int     g_cur[MAXN];
__device__ __align__(16) int     g_col[MAXE];
__device__ __align__(16) int     g_part[64];
// Pre-split/transposed/swizzled W images (one per layer):
// [kh0: Bhi 16KB | Blo 16KB][kh1: Bhi 16KB | Blo 16KB]  (Bt[n][k] bf16, SW128)
__device__ __align__(16) uint8_t g_wb1[65536];
__device__ __align__(16) uint8_t g_wb2[65536];

// ---------------------------------------------------------------------------
// Helpers (sm_80+ only: ldmatrix + mma.sync — NO tcgen05, target is sm_103)
// ---------------------------------------------------------------------------
__device__ __forceinline__ uint32_t swz128(uint32_t off) {
    return off ^ ((off >> 3) & 0x70);
}
__device__ __forceinline__ uint32_t smem_u32(const void* p) {
    return (uint32_t)__cvta_generic_to_shared(p);
}

__device__ __forceinline__ void ldsm_x4(uint32_t& r0, uint32_t& r1,
                                        uint32_t& r2, uint32_t& r3, uint32_t addr) {
    asm volatile("ldmatrix.sync.aligned.m8n8.x4.shared.b16 {%0,%1,%2,%3}, [%4];"
                 : "=r"(r0), "=r"(r1), "=r"(r2), "=r"(r3) : "r"(addr));
}
__device__ __forceinline__ void ldsm_x2(uint32_t& r0, uint32_t& r1, uint32_t addr) {
    asm volatile("ldmatrix.sync.aligned.m8n8.x2.shared.b16 {%0,%1}, [%2];"
                 : "=r"(r0), "=r"(r1) : "r"(addr));
}
__device__ __forceinline__ void mma_bf16(float& d0, float& d1, float& d2, float& d3,
                                         uint32_t a0, uint32_t a1, uint32_t a2, uint32_t a3,
                                         uint32_t b0, uint32_t b1) {
    asm volatile(
        "mma.sync.aligned.m16n8k16.row.col.f32.bf16.bf16.f32 "
        "{%0,%1,%2,%3}, {%4,%5,%6,%7}, {%8,%9}, {%0,%1,%2,%3};"
        : "+f"(d0), "+f"(d1), "+f"(d2), "+f"(d3)
        : "r"(a0), "r"(a1), "r"(a2), "r"(a3), "r"(b0), "r"(b1));
}

// ---------------------------------------------------------------------------
// W split helper (shared by the fused hist+wprep kernel)
// ---------------------------------------------------------------------------
__device__ __forceinline__ void wprep_one(const float* __restrict__ W,
                                          uint8_t* __restrict__ wb, int idx) {
    int nn = idx & 127;           // output col -> Bt row
    int k  = idx >> 7;            // input dim  -> Bt col
    float v = W[k * DD + nn];
    __nv_bfloat16 hi = __float2bfloat16(v);
    __nv_bfloat16 lo = __float2bfloat16(v - __bfloat162float(hi));
    int half = k >> 6, kk = k & 63;
    uint32_t off = swz128((uint32_t)(nn * 128 + kk * 2));
    *(__nv_bfloat16*)(wb + half * 32768 + off)         = hi;
    *(__nv_bfloat16*)(wb + half * 32768 + 16384 + off) = lo;
}

// ---------------------------------------------------------------------------
// Fused: histogram of dst (blocks < eb, 4 edges/thread) + W1/W2 prep
// ---------------------------------------------------------------------------
__global__ void k_hist_wprep(const int* __restrict__ dst, int* __restrict__ cnt,
                             int E, int eb,
                             const float* __restrict__ W1, uint8_t* __restrict__ wb1,
                             const float* __restrict__ W2, uint8_t* __restrict__ wb2) {
    int b = blockIdx.x;
    if (b < eb) {
        int i = (b * blockDim.x + threadIdx.x) * 4;
        if (i + 3 < E) {
            int4 d = *(const int4*)(dst + i);
            atomicAdd(&cnt[d.x], 1);
            atomicAdd(&cnt[d.y], 1);
            atomicAdd(&cnt[d.z], 1);
            atomicAdd(&cnt[d.w], 1);
        } else {
            for (int j = 0; j < 4; j++)
                if (i + j < E) atomicAdd(&cnt[dst[i + j]], 1);
        }
    } else if (b < eb + 64) {
        wprep_one(W1, wb1, (b - eb) * 256 + threadIdx.x);
    } else {
        wprep_one(W2, wb2, (b - eb - 64) * 256 + threadIdx.x);
    }
}

// ---------------------------------------------------------------------------
// 2-phase exclusive scan (+ dinv epilogue). Phase 1: per-block (1024) sums.
// ---------------------------------------------------------------------------
__global__ __launch_bounds__(256) void k_scan_partial(const int* __restrict__ cnt,
                                                      int* __restrict__ part, int n) {
    __shared__ int sh[8];
    int tid  = threadIdx.x;
    int base = blockIdx.x * 1024 + tid * 4;
    int s = 0;
    if (base + 3 < n) {
        int4 v = *(const int4*)(cnt + base);
        s = v.x + v.y + v.z + v.w;
    } else {
        for (int j = 0; j < 4; j++)
            if (base + j < n) s += cnt[base + j];
    }
#pragma unroll
    for (int o = 16; o; o >>= 1) s += __shfl_down_sync(0xffffffffu, s, o);
    if ((tid & 31) == 0) sh[tid >> 5] = s;
    __syncthreads();
    if (tid < 8) {
        s = sh[tid];
#pragma unroll
        for (int o = 4; o; o >>= 1) s += __shfl_down_sync(0x000000ffu, s, o);
        if (tid == 0) part[blockIdx.x] = s;
    }
}

// Phase 2 (fused tops-scan): every block redundantly scans the <=64 partials
// in-register, takes its own exclusive offset, then does the downsweep.
__global__ __launch_bounds__(256) void k_scan_down(const int* __restrict__ cnt,
                                                   const int* __restrict__ part,
                                                   int* __restrict__ rowptr,
                                                   int* __restrict__ cur,
                                                   float* __restrict__ dinv,
                                                   int n, int nb) {
    __shared__ int wsum[8];
    __shared__ int porig[64];
    __shared__ int pincl[64];
    int tid  = threadIdx.x;
    int lane = tid & 31, wid = tid >> 5;

    if (tid < 64) {
        int v = (tid < nb) ? part[tid] : 0;
        porig[tid] = v;
        int x = v;
#pragma unroll
        for (int o = 1; o < 32; o <<= 1) {
            int u = __shfl_up_sync(0xffffffffu, x, o);
            if (lane >= o) x += u;
        }
        pincl[tid] = x;
    }
    __syncthreads();
    int bi = blockIdx.x;
    int bincl = pincl[bi] + ((bi >= 32) ? pincl[31] : 0);
    int bexc  = bincl - porig[bi];
    if (bi == nb - 1 && tid == 0) rowptr[n] = bincl;

    int base = bi * 1024 + tid * 4;

    int4 c = make_int4(0, 0, 0, 0);
    if (base + 3 < n) c = *(const int4*)(cnt + base);
    else {
        int* cp = (int*)&c;
        for (int j = 0; j < 4; j++) cp[j] = (base + j < n) ? cnt[base + j] : 0;
    }
    int s0 = c.x, s1 = s0 + c.y, s2 = s1 + c.z, s3 = s2 + c.w;
    int ts = s3, sc = ts;
#pragma unroll
    for (int o = 1; o < 32; o <<= 1) {
        int u = __shfl_up_sync(0xffffffffu, sc, o);
        if (lane >= o) sc += u;
    }
    if (lane == 31) wsum[wid] = sc;
    __syncthreads();
    if (wid == 0) {
        int w = (lane < 8) ? wsum[lane] : 0;
#pragma unroll
        for (int o = 1; o < 8; o <<= 1) {
            int u = __shfl_up_sync(0xffffffffu, w, o);
            if (lane >= o) w += u;
        }
        if (lane < 8) wsum[lane] = w;
    }
    __syncthreads();

    int off = bexc + (wid ? wsum[wid - 1] : 0) + (sc - ts);
    if (base + 3 < n) {
        int4 r = make_int4(off, off + s0, off + s1, off + s2);
        *(int4*)(rowptr + base) = r;
        *(int4*)(cur + base)    = r;
        float4 dv = make_float4(rsqrtf((float)(c.x + 1)), rsqrtf((float)(c.y + 1)),
                                rsqrtf((float)(c.z + 1)), rsqrtf((float)(c.w + 1)));
        *(float4*)(dinv + base) = dv;
    } else {
        int rr[4] = {off, off + s0, off + s1, off + s2};
        int* cp = (int*)&c;
        for (int j = 0; j < 4; j++)
            if (base + j < n) {
                rowptr[base + j] = rr[j];
                cur[base + j]    = rr[j];
                dinv[base + j]   = rsqrtf((float)(cp[j] + 1));
            }
    }
}

// ---------------------------------------------------------------------------
// GEMM device body (split bf16 via mma.sync, fp32 accum, fp16 out)
// Called with bid = logical tile index; whole 256-thread block participates.
// ---------------------------------------------------------------------------
__device__ void gemm_body(char* sm, uint32_t sbase, int bid,
                          const float* __restrict__ A, const uint8_t* __restrict__ wb,
                          const float* __restrict__ dinv, __half* __restrict__ Ch,
                          int n) {
    int tid  = threadIdx.x;
    int wid  = tid >> 5, lane = tid & 31;
    int row0 = bid * 128;

    int mrow0 = (wid & 3) * 32;
    int ncol0 = (wid >> 2) * 64;

    float acc[2][8][4];
#pragma unroll
    for (int i = 0; i < 2; i++)
#pragma unroll
        for (int j = 0; j < 8; j++)
#pragma unroll
            for (int q = 0; q < 4; q++) acc[i][j][q] = 0.0f;

    const float4* A4 = (const float4*)A;

    for (int kh = 0; kh < 2; kh++) {
        const float4* wb4 = (const float4*)(wb + kh * 32768);
#pragma unroll
        for (int t = 0; t < 8; t++) {
            int i = tid + t * 256;
            *(float4*)(sm + 32768 + i * 16) = wb4[i];
        }
#pragma unroll
        for (int t = 0; t < 8; t++) {
            int i  = tid + t * 256;
            int m  = i >> 4;
            int f4 = i & 15;
            int gr = row0 + m;
            float4 v = (gr < n) ? A4[(size_t)gr * 32 + kh * 16 + f4]
                                : make_float4(0.f, 0.f, 0.f, 0.f);
            __nv_bfloat16 hx = __float2bfloat16(v.x);
            __nv_bfloat16 hy = __float2bfloat16(v.y);
            __nv_bfloat16 hz = __float2bfloat16(v.z);
            __nv_bfloat16 hw = __float2bfloat16(v.w);
            __nv_bfloat162 h0, h1, l0, l1;
            h0.x = hx; h0.y = hy; h1.x = hz; h1.y = hw;
            l0.x = __float2bfloat16(v.x - __bfloat162float(hx));
            l0.y = __float2bfloat16(v.y - __bfloat162float(hy));
            l1.x = __float2bfloat16(v.z - __bfloat162float(hz));
            l1.y = __float2bfloat16(v.w - __bfloat162float(hw));
            uint32_t off = swz128((uint32_t)(m * 128 + f4 * 8));
            *(__nv_bfloat162*)(sm + off)             = h0;
            *(__nv_bfloat162*)(sm + off + 4)         = h1;
            *(__nv_bfloat162*)(sm + 16384 + off)     = l0;
            *(__nv_bfloat162*)(sm + 16384 + off + 4) = l1;
        }
        __syncthreads();

#pragma unroll
        for (int k16 = 0; k16 < 4; k16++) {
            int kbyte = k16 * 32;
            uint32_t afh[2][4], afl[2][4];
#pragma unroll
            for (int mt = 0; mt < 2; mt++) {
                int mrow = mrow0 + mt * 16 + (lane & 7) + ((lane & 8) ? 8 : 0);
                int kb   = kbyte + ((lane & 16) ? 16 : 0);
                uint32_t a = sbase + swz128((uint32_t)(mrow * 128 + kb));
                ldsm_x4(afh[mt][0], afh[mt][1], afh[mt][2], afh[mt][3], a);
                ldsm_x4(afl[mt][0], afl[mt][1], afl[mt][2], afl[mt][3], a + 16384);
            }
#pragma unroll
            for (int nt = 0; nt < 8; nt++) {
                int nrow = ncol0 + nt * 8 + (lane & 7);
                int kb   = kbyte + ((lane & 8) ? 16 : 0);
                uint32_t baddr = sbase + 32768 + swz128((uint32_t)(nrow * 128 + kb));
                uint32_t bh0, bh1, bl0, bl1;
                ldsm_x2(bh0, bh1, baddr);
                ldsm_x2(bl0, bl1, baddr + 16384);
#pragma unroll
                for (int mt = 0; mt < 2; mt++) {
                    mma_bf16(acc[mt][nt][0], acc[mt][nt][1], acc[mt][nt][2], acc[mt][nt][3],
                             afh[mt][0], afh[mt][1], afh[mt][2], afh[mt][3], bh0, bh1);
                    mma_bf16(acc[mt][nt][0], acc[mt][nt][1], acc[mt][nt][2], acc[mt][nt][3],
                             afh[mt][0], afh[mt][1], afh[mt][2], afh[mt][3], bl0, bl1);
                    mma_bf16(acc[mt][nt][0], acc[mt][nt][1], acc[mt][nt][2], acc[mt][nt][3],
                             afl[mt][0], afl[mt][1], afl[mt][2], afl[mt][3], bh0, bh1);
                }
            }
        }
        __syncthreads();
    }

#pragma unroll
    for (int mt = 0; mt < 2; mt++) {
        int r1 = row0 + mrow0 + mt * 16 + (lane >> 2);
        int r2 = r1 + 8;
        float s1 = (r1 < n) ? dinv[r1] : 0.f;
        float s2 = (r2 < n) ? dinv[r2] : 0.f;
#pragma unroll
        for (int nt = 0; nt < 8; nt++) {
            int col = ncol0 + nt * 8 + ((lane & 3) << 1);
            if (r1 < n)
                *(__half2*)(Ch + (size_t)r1 * DD + col) =
                    __floats2half2_rn(acc[mt][nt][0] * s1, acc[mt][nt][1] * s1);
            if (r2 < n)
                *(__half2*)(Ch + (size_t)r2 * DD + col) =
                    __floats2half2_rn(acc[mt][nt][2] * s2, acc[mt][nt][3] * s2);
        }
    }
}

static const uint32_t GEMM_SMEM = 65536;

// Plain GEMM kernel (layer 2)
__global__ void __launch_bounds__(256)
k_gemm_mma(const float* __restrict__ A, const uint8_t* __restrict__ wb,
           const float* __restrict__ dinv, __half* __restrict__ Ch, int n) {
    extern __shared__ char sm[];
    gemm_body(sm, smem_u32(sm), blockIdx.x, A, wb, dinv, Ch, n);
}

// ---------------------------------------------------------------------------
// Fused: CSR fill (blocks < fb, 4 edges/thread) + layer-1 GEMM (blocks >= fb).
// Both depend only on scan_down output; the GPU overlaps them.
// ---------------------------------------------------------------------------
__global__ void __launch_bounds__(256)
k_fill_gemm(const int* __restrict__ src, const int* __restrict__ dst,
            int* __restrict__ cur, int* __restrict__ col, int E, int fb,
            const float* __restrict__ A, const uint8_t* __restrict__ wb,
            const float* __restrict__ dinv, __half* __restrict__ Ch, int n) {
    extern __shared__ char sm[];
    int b = blockIdx.x;
    if (b < fb) {
        int i = (b * blockDim.x + threadIdx.x) * 4;
        if (i + 3 < E) {
            int4 s = *(const int4*)(src + i);
            int4 d = *(const int4*)(dst + i);
            int p0 = atomicAdd(&cur[d.x], 1);
            int p1 = atomicAdd(&cur[d.y], 1);
            int p2 = atomicAdd(&cur[d.z], 1);
            int p3 = atomicAdd(&cur[d.w], 1);
            col[p0] = s.x; col[p1] = s.y; col[p2] = s.z; col[p3] = s.w;
        } else {
            for (int j = 0; j < 4; j++)
                if (i + j < E) col[atomicAdd(&cur[dst[i + j]], 1)] = src[i + j];
        }
    } else {
        gemm_body(sm, smem_u32(sm), b - fb, A, wb, dinv, Ch, n);
    }
}

// ---------------------------------------------------------------------------
// Fused CSR gather + self-loop + bias + ELU.  (round-9 proven shape)
// TWO nodes per warp: lanes 0-15 -> node 2w, lanes 16-31 -> node 2w+1.
// Lane owns a uint4 (8 halves = cols hl*8..hl*8+8). LDG.128 per edge.
// ---------------------------------------------------------------------------
__device__ __forceinline__ float eluf(float x) { return x > 0.0f ? x : expm1f(x); }

__device__ __forceinline__ void acc_h8(float4& a0, float4& a1, uint4 u) {
    float2 f0 = __half22float2(*(const __half2*)&u.x);
    float2 f1 = __half22float2(*(const __half2*)&u.y);
    float2 f2 = __half22float2(*(const __half2*)&u.z);
    float2 f3 = __half22float2(*(const __half2*)&u.w);
    a0.x += f0.x; a0.y += f0.y; a0.z += f1.x; a0.w += f1.y;
    a1.x += f2.x; a1.y += f2.y; a1.z += f3.x; a1.w += f3.y;
}

__global__ __launch_bounds__(256) void k_gather(const __half* __restrict__ hp,
                                                const int* __restrict__ rowptr,
                                                const int* __restrict__ colv,
                                                const float* __restrict__ dinv,
                                                const float* __restrict__ b,
                                                float* __restrict__ outp, int n) {
    int lane = threadIdx.x & 31;
    int half = lane >> 4;
    int hl   = lane & 15;
    int d    = (blockIdx.x * 8 + (threadIdx.x >> 5)) * 2 + half;
    uint32_t hmask = half ? 0xFFFF0000u : 0x0000FFFFu;

    bool valid = d < n;
    int dd     = valid ? d : 0;

    const uint4* hp4 = (const uint4*)hp;   // 16 uint4 (8 halves each) per row

    int start = rowptr[dd];
    int end   = valid ? rowptr[dd + 1] : start;

    float4 a0 = make_float4(0.f, 0.f, 0.f, 0.f);
    float4 a1 = make_float4(0.f, 0.f, 0.f, 0.f);
    acc_h8(a0, a1, hp4[(size_t)dd * 16 + hl]);   // self-loop

    for (int base = start; base < end; base += 16) {
        int cnt  = min(16, end - base);
        int sidx = (base + hl < end) ? colv[base + hl] : 0;
        int j = 0;
        for (; j + 4 <= cnt; j += 4) {
            int s0 = __shfl_sync(hmask, sidx, j,     16);
            int s1 = __shfl_sync(hmask, sidx, j + 1, 16);
            int s2 = __shfl_sync(hmask, sidx, j + 2, 16);
            int s3 = __shfl_sync(hmask, sidx, j + 3, 16);
            uint4 u0 = hp4[(size_t)s0 * 16 + hl];
            uint4 u1 = hp4[(size_t)s1 * 16 + hl];
            uint4 u2 = hp4[(size_t)s2 * 16 + hl];
            uint4 u3 = hp4[(size_t)s3 * 16 + hl];
            acc_h8(a0, a1, u0);
            acc_h8(a0, a1, u1);
            acc_h8(a0, a1, u2);
            acc_h8(a0, a1, u3);
        }
        for (; j < cnt; j++) {
            int s = __shfl_sync(hmask, sidx, j, 16);
            acc_h8(a0, a1, hp4[(size_t)s * 16 + hl]);
        }
    }

    if (valid) {
        float w = dinv[dd];
        float4 b0 = ((const float4*)b)[hl * 2];
        float4 b1 = ((const float4*)b)[hl * 2 + 1];
        a0.x = eluf(a0.x * w + b0.x);
        a0.y = eluf(a0.y * w + b0.y);
        a0.z = eluf(a0.z * w + b0.z);
        a0.w = eluf(a0.w * w + b0.w);
        a1.x = eluf(a1.x * w + b1.x);
        a1.y = eluf(a1.y * w + b1.y);
        a1.z = eluf(a1.z * w + b1.z);
        a1.w = eluf(a1.w * w + b1.w);
        ((float4*)outp)[(size_t)dd * 32 + hl * 2]     = a0;
        ((float4*)outp)[(size_t)dd * 32 + hl * 2 + 1] = a1;
    }
}

// ---------------------------------------------------------------------------
// Launch
// ---------------------------------------------------------------------------
extern "C" void kernel_launch(void* const* d_in, const int* in_sizes, int n_in,
                              void* d_out, int out_size) {
    const float* x  = (const float*)d_in[0];
    const int*   ei = (const int*)d_in[1];
    const float* W1 = (const float*)d_in[2];
    const float* b1 = (const float*)d_in[3];
    const float* W2 = (const float*)d_in[4];
    const float* b2 = (const float*)d_in[5];
    float* out = (float*)d_out;

    int N = in_sizes[0] / DD;
    int E = in_sizes[1] / 2;
    const int* src = ei;
    const int* dst = ei + E;

    float *dinv, *buf2;
    __half* hbuf;
    int *cnt, *rowptr, *cur, *col, *part;
    uint8_t *wb1, *wb2;
    cudaGetSymbolAddress((void**)&dinv, g_dinv);
    cudaGetSymbolAddress((void**)&hbuf, g_hbuf);
    cudaGetSymbolAddress((void**)&buf2, g_buf2);
    cudaGetSymbolAddress((void**)&cnt, g_cnt);
    cudaGetSymbolAddress((void**)&rowptr, g_rowptr);
    cudaGetSymbolAddress((void**)&cur, g_cur);
    cudaGetSymbolAddress((void**)&col, g_col);
    cudaGetSymbolAddress((void**)&part, g_part);
    cudaGetSymbolAddress((void**)&wb1, g_wb1);
    cudaGetSymbolAddress((void**)&wb2, g_wb2);

    cudaFuncSetAttribute(k_gemm_mma, cudaFuncAttributeMaxDynamicSharedMemorySize,
                         GEMM_SMEM);
    cudaFuncSetAttribute(k_fill_gemm, cudaFuncAttributeMaxDynamicSharedMemorySize,
                         GEMM_SMEM);

    const int T  = 256;
    int nb       = (N + 1023) / 1024;          // <= 64 partials
    int egrid4   = (E / 4 + T - 1) / T;        // 4 edges/thread kernels
    int gemm_grid   = (N + 127) / 128;
    int gather_grid = (N + 15) / 16;           // 8 warps/block, 2 nodes/warp

    // CSR build + normalization (+ fused W prep)
    cudaMemsetAsync(cnt, 0, (size_t)N * sizeof(int));
    k_hist_wprep<<<egrid4 + 128, T>>>(dst, cnt, E, egrid4, W1, wb1, W2, wb2);
    k_scan_partial<<<nb, T>>>(cnt, part, N);
    k_scan_down<<<nb, T>>>(cnt, part, rowptr, cur, dinv, N, nb);

    // Fused: CSR fill + layer-1 GEMM (independent work, overlapped)
    k_fill_gemm<<<egrid4 + gemm_grid, T, GEMM_SMEM>>>(
        src, dst, cur, col, E, egrid4, x, wb1, dinv, hbuf, N);

    // Layer 1 gather
    k_gather<<<gather_grid, 256>>>(hbuf, rowptr, col, dinv, b1, buf2, N);

    // Layer 2
    k_gemm_mma<<<gemm_grid, 256, GEMM_SMEM>>>(buf2, wb2, dinv, hbuf, N);
    k_gather<<<gather_grid, 256>>>(hbuf, rowptr, col, dinv, b2, out, N);
}

// round 13
// speedup vs baseline: 1.0822x; 1.0185x over previous
#include <cuda_runtime.h>
#include <cuda_bf16.h>
#include <cuda_fp16.h>
#include <math.h>
#include <stdint.h>

#define DD   128
#define MAXN 50000
#define MAXE 800000

// Scratch (allocation-free rule: __device__ globals)
__device__ __align__(16) float   g_dinv[MAXN];
__device__ __align__(16) __half  g_hbuf[(size_t)MAXN * DD];  // fp16 messages
__device__ __align__(16) float   g_buf2[(size_t)MAXN * DD];  // fp32 activation
__device__ __align__(16) int     g_cnt[MAXN];
__device__ __align__(16) int     g_rowptr[MAXN + 4];
__device__ __align__(16) int     g_cur[MAXN];
__device__ __align__(16) int     g_col[MAXE];
__device__ __align__(16) int     g_part[64];
// Pre-split/transposed/swizzled W images (one per layer):
// [kh0: Bhi 16KB | Blo 16KB][kh1: Bhi 16KB | Blo 16KB]  (Bt[n][k] bf16, SW128)
__device__ __align__(16) uint8_t g_wb1[65536];
__device__ __align__(16) uint8_t g_wb2[65536];

// ---------------------------------------------------------------------------
// Helpers (sm_80+ only: ldmatrix + mma.sync — NO tcgen05, target is sm_103)
// ---------------------------------------------------------------------------
__device__ __forceinline__ uint32_t swz128(uint32_t off) {
    return off ^ ((off >> 3) & 0x70);
}
__device__ __forceinline__ uint32_t smem_u32(const void* p) {
    return (uint32_t)__cvta_generic_to_shared(p);
}

__device__ __forceinline__ void ldsm_x4(uint32_t& r0, uint32_t& r1,
                                        uint32_t& r2, uint32_t& r3, uint32_t addr) {
    asm volatile("ldmatrix.sync.aligned.m8n8.x4.shared.b16 {%0,%1,%2,%3}, [%4];"
                 : "=r"(r0), "=r"(r1), "=r"(r2), "=r"(r3) : "r"(addr));
}
__device__ __forceinline__ void ldsm_x2(uint32_t& r0, uint32_t& r1, uint32_t addr) {
    asm volatile("ldmatrix.sync.aligned.m8n8.x2.shared.b16 {%0,%1}, [%2];"
                 : "=r"(r0), "=r"(r1) : "r"(addr));
}
__device__ __forceinline__ void mma_bf16(float& d0, float& d1, float& d2, float& d3,
                                         uint32_t a0, uint32_t a1, uint32_t a2, uint32_t a3,
                                         uint32_t b0, uint32_t b1) {
    asm volatile(
        "mma.sync.aligned.m16n8k16.row.col.f32.bf16.bf16.f32 "
        "{%0,%1,%2,%3}, {%4,%5,%6,%7}, {%8,%9}, {%0,%1,%2,%3};"
        : "+f"(d0), "+f"(d1), "+f"(d2), "+f"(d3)
        : "r"(a0), "r"(a1), "r"(a2), "r"(a3), "r"(b0), "r"(b1));
}

// ---------------------------------------------------------------------------
// W split helper (shared by the fused hist+wprep kernel)
// ---------------------------------------------------------------------------
__device__ __forceinline__ void wprep_one(const float* __restrict__ W,
                                          uint8_t* __restrict__ wb, int idx) {
    int nn = idx & 127;           // output col -> Bt row
    int k  = idx >> 7;            // input dim  -> Bt col
    float v = W[k * DD + nn];
    __nv_bfloat16 hi = __float2bfloat16(v);
    __nv_bfloat16 lo = __float2bfloat16(v - __bfloat162float(hi));
    int half = k >> 6, kk = k & 63;
    uint32_t off = swz128((uint32_t)(nn * 128 + kk * 2));
    *(__nv_bfloat16*)(wb + half * 32768 + off)         = hi;
    *(__nv_bfloat16*)(wb + half * 32768 + 16384 + off) = lo;
}

// ---------------------------------------------------------------------------
// Fused: histogram of dst (blocks < eb, 4 edges/thread) + W1/W2 prep
// ---------------------------------------------------------------------------
__global__ void k_hist_wprep(const int* __restrict__ dst, int* __restrict__ cnt,
                             int E, int eb,
                             const float* __restrict__ W1, uint8_t* __restrict__ wb1,
                             const float* __restrict__ W2, uint8_t* __restrict__ wb2) {
    int b = blockIdx.x;
    if (b < eb) {
        int i = (b * blockDim.x + threadIdx.x) * 4;
        if (i + 3 < E) {
            int4 d = *(const int4*)(dst + i);
            atomicAdd(&cnt[d.x], 1);
            atomicAdd(&cnt[d.y], 1);
            atomicAdd(&cnt[d.z], 1);
            atomicAdd(&cnt[d.w], 1);
        } else {
            for (int j = 0; j < 4; j++)
                if (i + j < E) atomicAdd(&cnt[dst[i + j]], 1);
        }
    } else if (b < eb + 64) {
        wprep_one(W1, wb1, (b - eb) * 256 + threadIdx.x);
    } else {
        wprep_one(W2, wb2, (b - eb - 64) * 256 + threadIdx.x);
    }
}

// ---------------------------------------------------------------------------
// 2-phase exclusive scan (+ dinv epilogue). Phase 1: per-block (1024) sums.
// ---------------------------------------------------------------------------
__global__ __launch_bounds__(256) void k_scan_partial(const int* __restrict__ cnt,
                                                      int* __restrict__ part, int n) {
    __shared__ int sh[8];
    int tid  = threadIdx.x;
    int base = blockIdx.x * 1024 + tid * 4;
    int s = 0;
    if (base + 3 < n) {
        int4 v = *(const int4*)(cnt + base);
        s = v.x + v.y + v.z + v.w;
    } else {
        for (int j = 0; j < 4; j++)
            if (base + j < n) s += cnt[base + j];
    }
#pragma unroll
    for (int o = 16; o; o >>= 1) s += __shfl_down_sync(0xffffffffu, s, o);
    if ((tid & 31) == 0) sh[tid >> 5] = s;
    __syncthreads();
    if (tid < 8) {
        s = sh[tid];
#pragma unroll
        for (int o = 4; o; o >>= 1) s += __shfl_down_sync(0x000000ffu, s, o);
        if (tid == 0) part[blockIdx.x] = s;
    }
}

// Phase 2 (fused tops-scan): every block redundantly scans the <=64 partials
// in-register, takes its own exclusive offset, then does the downsweep.
__global__ __launch_bounds__(256) void k_scan_down(const int* __restrict__ cnt,
                                                   const int* __restrict__ part,
                                                   int* __restrict__ rowptr,
                                                   int* __restrict__ cur,
                                                   float* __restrict__ dinv,
                                                   int n, int nb) {
    __shared__ int wsum[8];
    __shared__ int porig[64];
    __shared__ int pincl[64];
    int tid  = threadIdx.x;
    int lane = tid & 31, wid = tid >> 5;

    if (tid < 64) {
        int v = (tid < nb) ? part[tid] : 0;
        porig[tid] = v;
        int x = v;
#pragma unroll
        for (int o = 1; o < 32; o <<= 1) {
            int u = __shfl_up_sync(0xffffffffu, x, o);
            if (lane >= o) x += u;
        }
        pincl[tid] = x;
    }
    __syncthreads();
    int bi = blockIdx.x;
    int bincl = pincl[bi] + ((bi >= 32) ? pincl[31] : 0);
    int bexc  = bincl - porig[bi];
    if (bi == nb - 1 && tid == 0) rowptr[n] = bincl;

    int base = bi * 1024 + tid * 4;

    int4 c = make_int4(0, 0, 0, 0);
    if (base + 3 < n) c = *(const int4*)(cnt + base);
    else {
        int* cp = (int*)&c;
        for (int j = 0; j < 4; j++) cp[j] = (base + j < n) ? cnt[base + j] : 0;
    }
    int s0 = c.x, s1 = s0 + c.y, s2 = s1 + c.z, s3 = s2 + c.w;
    int ts = s3, sc = ts;
#pragma unroll
    for (int o = 1; o < 32; o <<= 1) {
        int u = __shfl_up_sync(0xffffffffu, sc, o);
        if (lane >= o) sc += u;
    }
    if (lane == 31) wsum[wid] = sc;
    __syncthreads();
    if (wid == 0) {
        int w = (lane < 8) ? wsum[lane] : 0;
#pragma unroll
        for (int o = 1; o < 8; o <<= 1) {
            int u = __shfl_up_sync(0xffffffffu, w, o);
            if (lane >= o) w += u;
        }
        if (lane < 8) wsum[lane] = w;
    }
    __syncthreads();

    int off = bexc + (wid ? wsum[wid - 1] : 0) + (sc - ts);
    if (base + 3 < n) {
        int4 r = make_int4(off, off + s0, off + s1, off + s2);
        *(int4*)(rowptr + base) = r;
        *(int4*)(cur + base)    = r;
        float4 dv = make_float4(rsqrtf((float)(c.x + 1)), rsqrtf((float)(c.y + 1)),
                                rsqrtf((float)(c.z + 1)), rsqrtf((float)(c.w + 1)));
        *(float4*)(dinv + base) = dv;
    } else {
        int rr[4] = {off, off + s0, off + s1, off + s2};
        int* cp = (int*)&c;
        for (int j = 0; j < 4; j++)
            if (base + j < n) {
                rowptr[base + j] = rr[j];
                cur[base + j]    = rr[j];
                dinv[base + j]   = rsqrtf((float)(cp[j] + 1));
            }
    }
}

// ---------------------------------------------------------------------------
// GEMM device body (split bf16 via mma.sync, fp32 accum, fp16 out)
// Called with bid = logical tile index; whole 256-thread block participates.
// ---------------------------------------------------------------------------
__device__ void gemm_body(char* sm, uint32_t sbase, int bid,
                          const float* __restrict__ A, const uint8_t* __restrict__ wb,
                          const float* __restrict__ dinv, __half* __restrict__ Ch,
                          int n) {
    int tid  = threadIdx.x;
    int wid  = tid >> 5, lane = tid & 31;
    int row0 = bid * 128;

    int mrow0 = (wid & 3) * 32;
    int ncol0 = (wid >> 2) * 64;

    float acc[2][8][4];
#pragma unroll
    for (int i = 0; i < 2; i++)
#pragma unroll
        for (int j = 0; j < 8; j++)
#pragma unroll
            for (int q = 0; q < 4; q++) acc[i][j][q] = 0.0f;

    const float4* A4 = (const float4*)A;

    for (int kh = 0; kh < 2; kh++) {
        const float4* wb4 = (const float4*)(wb + kh * 32768);
#pragma unroll
        for (int t = 0; t < 8; t++) {
            int i = tid + t * 256;
            *(float4*)(sm + 32768 + i * 16) = wb4[i];
        }
#pragma unroll
        for (int t = 0; t < 8; t++) {
            int i  = tid + t * 256;
            int m  = i >> 4;
            int f4 = i & 15;
            int gr = row0 + m;
            float4 v = (gr < n) ? A4[(size_t)gr * 32 + kh * 16 + f4]
                                : make_float4(0.f, 0.f, 0.f, 0.f);
            __nv_bfloat16 hx = __float2bfloat16(v.x);
            __nv_bfloat16 hy = __float2bfloat16(v.y);
            __nv_bfloat16 hz = __float2bfloat16(v.z);
            __nv_bfloat16 hw = __float2bfloat16(v.w);
            __nv_bfloat162 h0, h1, l0, l1;
            h0.x = hx; h0.y = hy; h1.x = hz; h1.y = hw;
            l0.x = __float2bfloat16(v.x - __bfloat162float(hx));
            l0.y = __float2bfloat16(v.y - __bfloat162float(hy));
            l1.x = __float2bfloat16(v.z - __bfloat162float(hz));
            l1.y = __float2bfloat16(v.w - __bfloat162float(hw));
            uint32_t off = swz128((uint32_t)(m * 128 + f4 * 8));
            *(__nv_bfloat162*)(sm + off)             = h0;
            *(__nv_bfloat162*)(sm + off + 4)         = h1;
            *(__nv_bfloat162*)(sm + 16384 + off)     = l0;
            *(__nv_bfloat162*)(sm + 16384 + off + 4) = l1;
        }
        __syncthreads();

#pragma unroll
        for (int k16 = 0; k16 < 4; k16++) {
            int kbyte = k16 * 32;
            uint32_t afh[2][4], afl[2][4];
#pragma unroll
            for (int mt = 0; mt < 2; mt++) {
                int mrow = mrow0 + mt * 16 + (lane & 7) + ((lane & 8) ? 8 : 0);
                int kb   = kbyte + ((lane & 16) ? 16 : 0);
                uint32_t a = sbase + swz128((uint32_t)(mrow * 128 + kb));
                ldsm_x4(afh[mt][0], afh[mt][1], afh[mt][2], afh[mt][3], a);
                ldsm_x4(afl[mt][0], afl[mt][1], afl[mt][2], afl[mt][3], a + 16384);
            }
#pragma unroll
            for (int nt = 0; nt < 8; nt++) {
                int nrow = ncol0 + nt * 8 + (lane & 7);
                int kb   = kbyte + ((lane & 8) ? 16 : 0);
                uint32_t baddr = sbase + 32768 + swz128((uint32_t)(nrow * 128 + kb));
                uint32_t bh0, bh1, bl0, bl1;
                ldsm_x2(bh0, bh1, baddr);
                ldsm_x2(bl0, bl1, baddr + 16384);
#pragma unroll
                for (int mt = 0; mt < 2; mt++) {
                    mma_bf16(acc[mt][nt][0], acc[mt][nt][1], acc[mt][nt][2], acc[mt][nt][3],
                             afh[mt][0], afh[mt][1], afh[mt][2], afh[mt][3], bh0, bh1);
                    mma_bf16(acc[mt][nt][0], acc[mt][nt][1], acc[mt][nt][2], acc[mt][nt][3],
                             afh[mt][0], afh[mt][1], afh[mt][2], afh[mt][3], bl0, bl1);
                    mma_bf16(acc[mt][nt][0], acc[mt][nt][1], acc[mt][nt][2], acc[mt][nt][3],
                             afl[mt][0], afl[mt][1], afl[mt][2], afl[mt][3], bh0, bh1);
                }
            }
        }
        __syncthreads();
    }

#pragma unroll
    for (int mt = 0; mt < 2; mt++) {
        int r1 = row0 + mrow0 + mt * 16 + (lane >> 2);
        int r2 = r1 + 8;
        float s1 = (r1 < n) ? dinv[r1] : 0.f;
        float s2 = (r2 < n) ? dinv[r2] : 0.f;
#pragma unroll
        for (int nt = 0; nt < 8; nt++) {
            int col = ncol0 + nt * 8 + ((lane & 3) << 1);
            if (r1 < n)
                *(__half2*)(Ch + (size_t)r1 * DD + col) =
                    __floats2half2_rn(acc[mt][nt][0] * s1, acc[mt][nt][1] * s1);
            if (r2 < n)
                *(__half2*)(Ch + (size_t)r2 * DD + col) =
                    __floats2half2_rn(acc[mt][nt][2] * s2, acc[mt][nt][3] * s2);
        }
    }
}

static const uint32_t GEMM_SMEM = 65536;

// Plain GEMM kernel (layer 2) — 2 blocks/SM so staging overlaps MMA across blocks
__global__ void __launch_bounds__(256, 2)
k_gemm_mma(const float* __restrict__ A, const uint8_t* __restrict__ wb,
           const float* __restrict__ dinv, __half* __restrict__ Ch, int n) {
    extern __shared__ char sm[];
    gemm_body(sm, smem_u32(sm), blockIdx.x, A, wb, dinv, Ch, n);
}

// ---------------------------------------------------------------------------
// Fused: CSR fill (blocks < fb, 4 edges/thread) + layer-1 GEMM (blocks >= fb).
// __launch_bounds__(256,2): <=128 regs so fill blocks aren't starved to 1/SM.
// ---------------------------------------------------------------------------
__global__ void __launch_bounds__(256, 2)
k_fill_gemm(const int* __restrict__ src, const int* __restrict__ dst,
            int* __restrict__ cur, int* __restrict__ col, int E, int fb,
            const float* __restrict__ A, const uint8_t* __restrict__ wb,
            const float* __restrict__ dinv, __half* __restrict__ Ch, int n) {
    extern __shared__ char sm[];
    int b = blockIdx.x;
    if (b < fb) {
        int i = (b * blockDim.x + threadIdx.x) * 4;
        if (i + 3 < E) {
            int4 s = *(const int4*)(src + i);
            int4 d = *(const int4*)(dst + i);
            int p0 = atomicAdd(&cur[d.x], 1);
            int p1 = atomicAdd(&cur[d.y], 1);
            int p2 = atomicAdd(&cur[d.z], 1);
            int p3 = atomicAdd(&cur[d.w], 1);
            col[p0] = s.x; col[p1] = s.y; col[p2] = s.z; col[p3] = s.w;
        } else {
            for (int j = 0; j < 4; j++)
                if (i + j < E) col[atomicAdd(&cur[dst[i + j]], 1)] = src[i + j];
        }
    } else {
        gemm_body(sm, smem_u32(sm), b - fb, A, wb, dinv, Ch, n);
    }
}

// ---------------------------------------------------------------------------
// Fused CSR gather + self-loop + bias + ELU.  (round-9 proven shape)
// TWO nodes per warp: lanes 0-15 -> node 2w, lanes 16-31 -> node 2w+1.
// Lane owns a uint4 (8 halves = cols hl*8..hl*8+8). LDG.128 per edge.
// ---------------------------------------------------------------------------
__device__ __forceinline__ float eluf(float x) { return x > 0.0f ? x : expm1f(x); }

__device__ __forceinline__ void acc_h8(float4& a0, float4& a1, uint4 u) {
    float2 f0 = __half22float2(*(const __half2*)&u.x);
    float2 f1 = __half22float2(*(const __half2*)&u.y);
    float2 f2 = __half22float2(*(const __half2*)&u.z);
    float2 f3 = __half22float2(*(const __half2*)&u.w);
    a0.x += f0.x; a0.y += f0.y; a0.z += f1.x; a0.w += f1.y;
    a1.x += f2.x; a1.y += f2.y; a1.z += f3.x; a1.w += f3.y;
}

__global__ __launch_bounds__(256) void k_gather(const __half* __restrict__ hp,
                                                const int* __restrict__ rowptr,
                                                const int* __restrict__ colv,
                                                const float* __restrict__ dinv,
                                                const float* __restrict__ b,
                                                float* __restrict__ outp, int n) {
    int lane = threadIdx.x & 31;
    int half = lane >> 4;
    int hl   = lane & 15;
    int d    = (blockIdx.x * 8 + (threadIdx.x >> 5)) * 2 + half;
    uint32_t hmask = half ? 0xFFFF0000u : 0x0000FFFFu;

    bool valid = d < n;
    int dd     = valid ? d : 0;

    const uint4* hp4 = (const uint4*)hp;   // 16 uint4 (8 halves each) per row

    int start = rowptr[dd];
    int end   = valid ? rowptr[dd + 1] : start;

    float4 a0 = make_float4(0.f, 0.f, 0.f, 0.f);
    float4 a1 = make_float4(0.f, 0.f, 0.f, 0.f);
    acc_h8(a0, a1, hp4[(size_t)dd * 16 + hl]);   // self-loop

    for (int base = start; base < end; base += 16) {
        int cnt  = min(16, end - base);
        int sidx = (base + hl < end) ? colv[base + hl] : 0;
        int j = 0;
        for (; j + 4 <= cnt; j += 4) {
            int s0 = __shfl_sync(hmask, sidx, j,     16);
            int s1 = __shfl_sync(hmask, sidx, j + 1, 16);
            int s2 = __shfl_sync(hmask, sidx, j + 2, 16);
            int s3 = __shfl_sync(hmask, sidx, j + 3, 16);
            uint4 u0 = hp4[(size_t)s0 * 16 + hl];
            uint4 u1 = hp4[(size_t)s1 * 16 + hl];
            uint4 u2 = hp4[(size_t)s2 * 16 + hl];
            uint4 u3 = hp4[(size_t)s3 * 16 + hl];
            acc_h8(a0, a1, u0);
            acc_h8(a0, a1, u1);
            acc_h8(a0, a1, u2);
            acc_h8(a0, a1, u3);
        }
        for (; j < cnt; j++) {
            int s = __shfl_sync(hmask, sidx, j, 16);
            acc_h8(a0, a1, hp4[(size_t)s * 16 + hl]);
        }
    }

    if (valid) {
        float w = dinv[dd];
        float4 b0 = ((const float4*)b)[hl * 2];
        float4 b1 = ((const float4*)b)[hl * 2 + 1];
        a0.x = eluf(a0.x * w + b0.x);
        a0.y = eluf(a0.y * w + b0.y);
        a0.z = eluf(a0.z * w + b0.z);
        a0.w = eluf(a0.w * w + b0.w);
        a1.x = eluf(a1.x * w + b1.x);
        a1.y = eluf(a1.y * w + b1.y);
        a1.z = eluf(a1.z * w + b1.z);
        a1.w = eluf(a1.w * w + b1.w);
        ((float4*)outp)[(size_t)dd * 32 + hl * 2]     = a0;
        ((float4*)outp)[(size_t)dd * 32 + hl * 2 + 1] = a1;
    }
}

// ---------------------------------------------------------------------------
// Launch
// ---------------------------------------------------------------------------
extern "C" void kernel_launch(void* const* d_in, const int* in_sizes, int n_in,
                              void* d_out, int out_size) {
    const float* x  = (const float*)d_in[0];
    const int*   ei = (const int*)d_in[1];
    const float* W1 = (const float*)d_in[2];
    const float* b1 = (const float*)d_in[3];
    const float* W2 = (const float*)d_in[4];
    const float* b2 = (const float*)d_in[5];
    float* out = (float*)d_out;

    int N = in_sizes[0] / DD;
    int E = in_sizes[1] / 2;
    const int* src = ei;
    const int* dst = ei + E;

    float *dinv, *buf2;
    __half* hbuf;
    int *cnt, *rowptr, *cur, *col, *part;
    uint8_t *wb1, *wb2;
    cudaGetSymbolAddress((void**)&dinv, g_dinv);
    cudaGetSymbolAddress((void**)&hbuf, g_hbuf);
    cudaGetSymbolAddress((void**)&buf2, g_buf2);
    cudaGetSymbolAddress((void**)&cnt, g_cnt);
    cudaGetSymbolAddress((void**)&rowptr, g_rowptr);
    cudaGetSymbolAddress((void**)&cur, g_cur);
    cudaGetSymbolAddress((void**)&col, g_col);
    cudaGetSymbolAddress((void**)&part, g_part);
    cudaGetSymbolAddress((void**)&wb1, g_wb1);
    cudaGetSymbolAddress((void**)&wb2, g_wb2);

    cudaFuncSetAttribute(k_gemm_mma, cudaFuncAttributeMaxDynamicSharedMemorySize,
                         GEMM_SMEM);
    cudaFuncSetAttribute(k_fill_gemm, cudaFuncAttributeMaxDynamicSharedMemorySize,
                         GEMM_SMEM);

    const int T  = 256;
    int nb       = (N + 1023) / 1024;          // <= 64 partials
    int egrid4   = (E / 4 + T - 1) / T;        // 4 edges/thread kernels
    int gemm_grid   = (N + 127) / 128;
    int gather_grid = (N + 15) / 16;           // 8 warps/block, 2 nodes/warp

    // CSR build + normalization (+ fused W prep)
    cudaMemsetAsync(cnt, 0, (size_t)N * sizeof(int));
    k_hist_wprep<<<egrid4 + 128, T>>>(dst, cnt, E, egrid4, W1, wb1, W2, wb2);
    k_scan_partial<<<nb, T>>>(cnt, part, N);
    k_scan_down<<<nb, T>>>(cnt, part, rowptr, cur, dinv, N, nb);

    // Fused: CSR fill + layer-1 GEMM (independent work, overlapped)
    k_fill_gemm<<<egrid4 + gemm_grid, T, GEMM_SMEM>>>(
        src, dst, cur, col, E, egrid4, x, wb1, dinv, hbuf, N);

    // Layer 1 gather
    k_gather<<<gather_grid, 256>>>(hbuf, rowptr, col, dinv, b1, buf2, N);

    // Layer 2
    k_gemm_mma<<<gemm_grid, 256, GEMM_SMEM>>>(buf2, wb2, dinv, hbuf, N);
    k_gather<<<gather_grid, 256>>>(hbuf, rowptr, col, dinv, b2, out, N);
}

// round 14
// speedup vs baseline: 1.0863x; 1.0039x over previous
#include <cuda_runtime.h>
#include <cuda_bf16.h>
#include <cuda_fp16.h>
#include <math.h>
#include <stdint.h>

#define DD   128
#define MAXN 50000
#define MAXE 800000

// Scratch (allocation-free rule: __device__ globals)
__device__ __align__(16) float   g_dinv[MAXN];
__device__ __align__(16) __half  g_hbuf[(size_t)MAXN * DD];  // fp16 messages
__device__ __align__(16) float   g_buf2[(size_t)MAXN * DD];  // fp32 activation
__device__ __align__(16) int     g_cnt[MAXN];
__device__ __align__(16) int     g_rowptr[MAXN + 4];
__device__ __align__(16) int     g_cur[MAXN];
__device__ __align__(16) int     g_col[MAXE];
__device__ __align__(16) int     g_part[64];
// Pre-split/transposed/swizzled W images (one per layer):
// [kh0: Bhi 16KB | Blo 16KB][kh1: Bhi 16KB | Blo 16KB]  (Bt[n][k] bf16, SW128)
__device__ __align__(16) uint8_t g_wb1[65536];
__device__ __align__(16) uint8_t g_wb2[65536];

// ---------------------------------------------------------------------------
// Helpers (sm_80+ only: ldmatrix + mma.sync — NO tcgen05, target is sm_103)
// ---------------------------------------------------------------------------
__device__ __forceinline__ uint32_t swz128(uint32_t off) {
    return off ^ ((off >> 3) & 0x70);
}
__device__ __forceinline__ uint32_t smem_u32(const void* p) {
    return (uint32_t)__cvta_generic_to_shared(p);
}

__device__ __forceinline__ void ldsm_x4(uint32_t& r0, uint32_t& r1,
                                        uint32_t& r2, uint32_t& r3, uint32_t addr) {
    asm volatile("ldmatrix.sync.aligned.m8n8.x4.shared.b16 {%0,%1,%2,%3}, [%4];"
                 : "=r"(r0), "=r"(r1), "=r"(r2), "=r"(r3) : "r"(addr));
}
__device__ __forceinline__ void ldsm_x2(uint32_t& r0, uint32_t& r1, uint32_t addr) {
    asm volatile("ldmatrix.sync.aligned.m8n8.x2.shared.b16 {%0,%1}, [%2];"
                 : "=r"(r0), "=r"(r1) : "r"(addr));
}
__device__ __forceinline__ void mma_bf16(float& d0, float& d1, float& d2, float& d3,
                                         uint32_t a0, uint32_t a1, uint32_t a2, uint32_t a3,
                                         uint32_t b0, uint32_t b1) {
    asm volatile(
        "mma.sync.aligned.m16n8k16.row.col.f32.bf16.bf16.f32 "
        "{%0,%1,%2,%3}, {%4,%5,%6,%7}, {%8,%9}, {%0,%1,%2,%3};"
        : "+f"(d0), "+f"(d1), "+f"(d2), "+f"(d3)
        : "r"(a0), "r"(a1), "r"(a2), "r"(a3), "r"(b0), "r"(b1));
}

// ---------------------------------------------------------------------------
// W split helper (shared by the fused hist+wprep kernel)
// ---------------------------------------------------------------------------
__device__ __forceinline__ void wprep_one(const float* __restrict__ W,
                                          uint8_t* __restrict__ wb, int idx) {
    int nn = idx & 127;           // output col -> Bt row
    int k  = idx >> 7;            // input dim  -> Bt col
    float v = W[k * DD + nn];
    __nv_bfloat16 hi = __float2bfloat16(v);
    __nv_bfloat16 lo = __float2bfloat16(v - __bfloat162float(hi));
    int half = k >> 6, kk = k & 63;
    uint32_t off = swz128((uint32_t)(nn * 128 + kk * 2));
    *(__nv_bfloat16*)(wb + half * 32768 + off)         = hi;
    *(__nv_bfloat16*)(wb + half * 32768 + 16384 + off) = lo;
}

// ---------------------------------------------------------------------------
// Fused: histogram of dst (blocks < eb, 4 edges/thread) + W1/W2 prep
// ---------------------------------------------------------------------------
__global__ void k_hist_wprep(const int* __restrict__ dst, int* __restrict__ cnt,
                             int E, int eb,
                             const float* __restrict__ W1, uint8_t* __restrict__ wb1,
                             const float* __restrict__ W2, uint8_t* __restrict__ wb2) {
    int b = blockIdx.x;
    if (b < eb) {
        int i = (b * blockDim.x + threadIdx.x) * 4;
        if (i + 3 < E) {
            int4 d = *(const int4*)(dst + i);
            atomicAdd(&cnt[d.x], 1);
            atomicAdd(&cnt[d.y], 1);
            atomicAdd(&cnt[d.z], 1);
            atomicAdd(&cnt[d.w], 1);
        } else {
            for (int j = 0; j < 4; j++)
                if (i + j < E) atomicAdd(&cnt[dst[i + j]], 1);
        }
    } else if (b < eb + 64) {
        wprep_one(W1, wb1, (b - eb) * 256 + threadIdx.x);
    } else {
        wprep_one(W2, wb2, (b - eb - 64) * 256 + threadIdx.x);
    }
}

// ---------------------------------------------------------------------------
// 2-phase exclusive scan (+ dinv epilogue). Phase 1: per-block (1024) sums.
// ---------------------------------------------------------------------------
__global__ __launch_bounds__(256) void k_scan_partial(const int* __restrict__ cnt,
                                                      int* __restrict__ part, int n) {
    __shared__ int sh[8];
    int tid  = threadIdx.x;
    int base = blockIdx.x * 1024 + tid * 4;
    int s = 0;
    if (base + 3 < n) {
        int4 v = *(const int4*)(cnt + base);
        s = v.x + v.y + v.z + v.w;
    } else {
        for (int j = 0; j < 4; j++)
            if (base + j < n) s += cnt[base + j];
    }
#pragma unroll
    for (int o = 16; o; o >>= 1) s += __shfl_down_sync(0xffffffffu, s, o);
    if ((tid & 31) == 0) sh[tid >> 5] = s;
    __syncthreads();
    if (tid < 8) {
        s = sh[tid];
#pragma unroll
        for (int o = 4; o; o >>= 1) s += __shfl_down_sync(0x000000ffu, s, o);
        if (tid == 0) part[blockIdx.x] = s;
    }
}

// Phase 2 (fused tops-scan): every block redundantly scans the <=64 partials
// in-register, takes its own exclusive offset, then does the downsweep.
__global__ __launch_bounds__(256) void k_scan_down(const int* __restrict__ cnt,
                                                   const int* __restrict__ part,
                                                   int* __restrict__ rowptr,
                                                   int* __restrict__ cur,
                                                   float* __restrict__ dinv,
                                                   int n, int nb) {
    __shared__ int wsum[8];
    __shared__ int porig[64];
    __shared__ int pincl[64];
    int tid  = threadIdx.x;
    int lane = tid & 31, wid = tid >> 5;

    if (tid < 64) {
        int v = (tid < nb) ? part[tid] : 0;
        porig[tid] = v;
        int x = v;
#pragma unroll
        for (int o = 1; o < 32; o <<= 1) {
            int u = __shfl_up_sync(0xffffffffu, x, o);
            if (lane >= o) x += u;
        }
        pincl[tid] = x;
    }
    __syncthreads();
    int bi = blockIdx.x;
    int bincl = pincl[bi] + ((bi >= 32) ? pincl[31] : 0);
    int bexc  = bincl - porig[bi];
    if (bi == nb - 1 && tid == 0) rowptr[n] = bincl;

    int base = bi * 1024 + tid * 4;

    int4 c = make_int4(0, 0, 0, 0);
    if (base + 3 < n) c = *(const int4*)(cnt + base);
    else {
        int* cp = (int*)&c;
        for (int j = 0; j < 4; j++) cp[j] = (base + j < n) ? cnt[base + j] : 0;
    }
    int s0 = c.x, s1 = s0 + c.y, s2 = s1 + c.z, s3 = s2 + c.w;
    int ts = s3, sc = ts;
#pragma unroll
    for (int o = 1; o < 32; o <<= 1) {
        int u = __shfl_up_sync(0xffffffffu, sc, o);
        if (lane >= o) sc += u;
    }
    if (lane == 31) wsum[wid] = sc;
    __syncthreads();
    if (wid == 0) {
        int w = (lane < 8) ? wsum[lane] : 0;
#pragma unroll
        for (int o = 1; o < 8; o <<= 1) {
            int u = __shfl_up_sync(0xffffffffu, w, o);
            if (lane >= o) w += u;
        }
        if (lane < 8) wsum[lane] = w;
    }
    __syncthreads();

    int off = bexc + (wid ? wsum[wid - 1] : 0) + (sc - ts);
    if (base + 3 < n) {
        int4 r = make_int4(off, off + s0, off + s1, off + s2);
        *(int4*)(rowptr + base) = r;
        *(int4*)(cur + base)    = r;
        float4 dv = make_float4(rsqrtf((float)(c.x + 1)), rsqrtf((float)(c.y + 1)),
                                rsqrtf((float)(c.z + 1)), rsqrtf((float)(c.w + 1)));
        *(float4*)(dinv + base) = dv;
    } else {
        int rr[4] = {off, off + s0, off + s1, off + s2};
        int* cp = (int*)&c;
        for (int j = 0; j < 4; j++)
            if (base + j < n) {
                rowptr[base + j] = rr[j];
                cur[base + j]    = rr[j];
                dinv[base + j]   = rsqrtf((float)(cp[j] + 1));
            }
    }
}

// ---------------------------------------------------------------------------
// CSR fill — standalone (no smem, high occupancy), 4 edges/thread
// ---------------------------------------------------------------------------
__global__ void k_fill(const int* __restrict__ src, const int* __restrict__ dst,
                       int* __restrict__ cur, int* __restrict__ col, int E) {
    int i = (blockIdx.x * blockDim.x + threadIdx.x) * 4;
    if (i + 3 < E) {
        int4 s = *(const int4*)(src + i);
        int4 d = *(const int4*)(dst + i);
        int p0 = atomicAdd(&cur[d.x], 1);
        int p1 = atomicAdd(&cur[d.y], 1);
        int p2 = atomicAdd(&cur[d.z], 1);
        int p3 = atomicAdd(&cur[d.w], 1);
        col[p0] = s.x; col[p1] = s.y; col[p2] = s.z; col[p3] = s.w;
    } else {
        for (int j = 0; j < 4; j++)
            if (i + j < E) col[atomicAdd(&cur[dst[i + j]], 1)] = src[i + j];
    }
}

// ---------------------------------------------------------------------------
// GEMM device body (split bf16 via mma.sync, fp32 accum, fp16 out)
// ---------------------------------------------------------------------------
__device__ void gemm_body(char* sm, uint32_t sbase, int bid,
                          const float* __restrict__ A, const uint8_t* __restrict__ wb,
                          const float* __restrict__ dinv, __half* __restrict__ Ch,
                          int n) {
    int tid  = threadIdx.x;
    int wid  = tid >> 5, lane = tid & 31;
    int row0 = bid * 128;

    int mrow0 = (wid & 3) * 32;
    int ncol0 = (wid >> 2) * 64;

    float acc[2][8][4];
#pragma unroll
    for (int i = 0; i < 2; i++)
#pragma unroll
        for (int j = 0; j < 8; j++)
#pragma unroll
            for (int q = 0; q < 4; q++) acc[i][j][q] = 0.0f;

    const float4* A4 = (const float4*)A;

    for (int kh = 0; kh < 2; kh++) {
        const float4* wb4 = (const float4*)(wb + kh * 32768);
#pragma unroll
        for (int t = 0; t < 8; t++) {
            int i = tid + t * 256;
            *(float4*)(sm + 32768 + i * 16) = wb4[i];
        }
#pragma unroll
        for (int t = 0; t < 8; t++) {
            int i  = tid + t * 256;
            int m  = i >> 4;
            int f4 = i & 15;
            int gr = row0 + m;
            float4 v = (gr < n) ? A4[(size_t)gr * 32 + kh * 16 + f4]
                                : make_float4(0.f, 0.f, 0.f, 0.f);
            __nv_bfloat16 hx = __float2bfloat16(v.x);
            __nv_bfloat16 hy = __float2bfloat16(v.y);
            __nv_bfloat16 hz = __float2bfloat16(v.z);
            __nv_bfloat16 hw = __float2bfloat16(v.w);
            __nv_bfloat162 h0, h1, l0, l1;
            h0.x = hx; h0.y = hy; h1.x = hz; h1.y = hw;
            l0.x = __float2bfloat16(v.x - __bfloat162float(hx));
            l0.y = __float2bfloat16(v.y - __bfloat162float(hy));
            l1.x = __float2bfloat16(v.z - __bfloat162float(hz));
            l1.y = __float2bfloat16(v.w - __bfloat162float(hw));
            uint32_t off = swz128((uint32_t)(m * 128 + f4 * 8));
            *(__nv_bfloat162*)(sm + off)             = h0;
            *(__nv_bfloat162*)(sm + off + 4)         = h1;
            *(__nv_bfloat162*)(sm + 16384 + off)     = l0;
            *(__nv_bfloat162*)(sm + 16384 + off + 4) = l1;
        }
        __syncthreads();

#pragma unroll
        for (int k16 = 0; k16 < 4; k16++) {
            int kbyte = k16 * 32;
            uint32_t afh[2][4], afl[2][4];
#pragma unroll
            for (int mt = 0; mt < 2; mt++) {
                int mrow = mrow0 + mt * 16 + (lane & 7) + ((lane & 8) ? 8 : 0);
                int kb   = kbyte + ((lane & 16) ? 16 : 0);
                uint32_t a = sbase + swz128((uint32_t)(mrow * 128 + kb));
                ldsm_x4(afh[mt][0], afh[mt][1], afh[mt][2], afh[mt][3], a);
                ldsm_x4(afl[mt][0], afl[mt][1], afl[mt][2], afl[mt][3], a + 16384);
            }
#pragma unroll
            for (int nt = 0; nt < 8; nt++) {
                int nrow = ncol0 + nt * 8 + (lane & 7);
                int kb   = kbyte + ((lane & 8) ? 16 : 0);
                uint32_t baddr = sbase + 32768 + swz128((uint32_t)(nrow * 128 + kb));
                uint32_t bh0, bh1, bl0, bl1;
                ldsm_x2(bh0, bh1, baddr);
                ldsm_x2(bl0, bl1, baddr + 16384);
#pragma unroll
                for (int mt = 0; mt < 2; mt++) {
                    mma_bf16(acc[mt][nt][0], acc[mt][nt][1], acc[mt][nt][2], acc[mt][nt][3],
                             afh[mt][0], afh[mt][1], afh[mt][2], afh[mt][3], bh0, bh1);
                    mma_bf16(acc[mt][nt][0], acc[mt][nt][1], acc[mt][nt][2], acc[mt][nt][3],
                             afh[mt][0], afh[mt][1], afh[mt][2], afh[mt][3], bl0, bl1);
                    mma_bf16(acc[mt][nt][0], acc[mt][nt][1], acc[mt][nt][2], acc[mt][nt][3],
                             afl[mt][0], afl[mt][1], afl[mt][2], afl[mt][3], bh0, bh1);
                }
            }
        }
        __syncthreads();
    }

#pragma unroll
    for (int mt = 0; mt < 2; mt++) {
        int r1 = row0 + mrow0 + mt * 16 + (lane >> 2);
        int r2 = r1 + 8;
        float s1 = (r1 < n) ? dinv[r1] : 0.f;
        float s2 = (r2 < n) ? dinv[r2] : 0.f;
#pragma unroll
        for (int nt = 0; nt < 8; nt++) {
            int col = ncol0 + nt * 8 + ((lane & 3) << 1);
            if (r1 < n)
                *(__half2*)(Ch + (size_t)r1 * DD + col) =
                    __floats2half2_rn(acc[mt][nt][0] * s1, acc[mt][nt][1] * s1);
            if (r2 < n)
                *(__half2*)(Ch + (size_t)r2 * DD + col) =
                    __floats2half2_rn(acc[mt][nt][2] * s2, acc[mt][nt][3] * s2);
        }
    }
}

static const uint32_t GEMM_SMEM = 65536;

// GEMM kernel — 2 blocks/SM so staging overlaps MMA across blocks
__global__ void __launch_bounds__(256, 2)
k_gemm_mma(const float* __restrict__ A, const uint8_t* __restrict__ wb,
           const float* __restrict__ dinv, __half* __restrict__ Ch, int n) {
    extern __shared__ char sm[];
    gemm_body(sm, smem_u32(sm), blockIdx.x, A, wb, dinv, Ch, n);
}

// ---------------------------------------------------------------------------
// Fused CSR gather + self-loop + bias + ELU.  (round-9 proven shape)
// TWO nodes per warp: lanes 0-15 -> node 2w, lanes 16-31 -> node 2w+1.
// Lane owns a uint4 (8 halves = cols hl*8..hl*8+8). LDG.128 per edge.
// ---------------------------------------------------------------------------
__device__ __forceinline__ float eluf(float x) { return x > 0.0f ? x : expm1f(x); }

__device__ __forceinline__ void acc_h8(float4& a0, float4& a1, uint4 u) {
    float2 f0 = __half22float2(*(const __half2*)&u.x);
    float2 f1 = __half22float2(*(const __half2*)&u.y);
    float2 f2 = __half22float2(*(const __half2*)&u.z);
    float2 f3 = __half22float2(*(const __half2*)&u.w);
    a0.x += f0.x; a0.y += f0.y; a0.z += f1.x; a0.w += f1.y;
    a1.x += f2.x; a1.y += f2.y; a1.z += f3.x; a1.w += f3.y;
}

__global__ __launch_bounds__(256) void k_gather(const __half* __restrict__ hp,
                                                const int* __restrict__ rowptr,
                                                const int* __restrict__ colv,
                                                const float* __restrict__ dinv,
                                                const float* __restrict__ b,
                                                float* __restrict__ outp, int n) {
    int lane = threadIdx.x & 31;
    int half = lane >> 4;
    int hl   = lane & 15;
    int d    = (blockIdx.x * 8 + (threadIdx.x >> 5)) * 2 + half;
    uint32_t hmask = half ? 0xFFFF0000u : 0x0000FFFFu;

    bool valid = d < n;
    int dd     = valid ? d : 0;

    const uint4* hp4 = (const uint4*)hp;   // 16 uint4 (8 halves each) per row

    int start = rowptr[dd];
    int end   = valid ? rowptr[dd + 1] : start;

    float4 a0 = make_float4(0.f, 0.f, 0.f, 0.f);
    float4 a1 = make_float4(0.f, 0.f, 0.f, 0.f);
    acc_h8(a0, a1, hp4[(size_t)dd * 16 + hl]);   // self-loop

    for (int base = start; base < end; base += 16) {
        int cnt  = min(16, end - base);
        int sidx = (base + hl < end) ? colv[base + hl] : 0;
        int j = 0;
        for (; j + 4 <= cnt; j += 4) {
            int s0 = __shfl_sync(hmask, sidx, j,     16);
            int s1 = __shfl_sync(hmask, sidx, j + 1, 16);
            int s2 = __shfl_sync(hmask, sidx, j + 2, 16);
            int s3 = __shfl_sync(hmask, sidx, j + 3, 16);
            uint4 u0 = hp4[(size_t)s0 * 16 + hl];
            uint4 u1 = hp4[(size_t)s1 * 16 + hl];
            uint4 u2 = hp4[(size_t)s2 * 16 + hl];
            uint4 u3 = hp4[(size_t)s3 * 16 + hl];
            acc_h8(a0, a1, u0);
            acc_h8(a0, a1, u1);
            acc_h8(a0, a1, u2);
            acc_h8(a0, a1, u3);
        }
        for (; j < cnt; j++) {
            int s = __shfl_sync(hmask, sidx, j, 16);
            acc_h8(a0, a1, hp4[(size_t)s * 16 + hl]);
        }
    }

    if (valid) {
        float w = dinv[dd];
        float4 b0 = ((const float4*)b)[hl * 2];
        float4 b1 = ((const float4*)b)[hl * 2 + 1];
        a0.x = eluf(a0.x * w + b0.x);
        a0.y = eluf(a0.y * w + b0.y);
        a0.z = eluf(a0.z * w + b0.z);
        a0.w = eluf(a0.w * w + b0.w);
        a1.x = eluf(a1.x * w + b1.x);
        a1.y = eluf(a1.y * w + b1.y);
        a1.z = eluf(a1.z * w + b1.z);
        a1.w = eluf(a1.w * w + b1.w);
        ((float4*)outp)[(size_t)dd * 32 + hl * 2]     = a0;
        ((float4*)outp)[(size_t)dd * 32 + hl * 2 + 1] = a1;
    }
}

// ---------------------------------------------------------------------------
// Launch — fork-join: k_fill runs on a side stream in parallel with GEMM-1.
// ---------------------------------------------------------------------------
extern "C" void kernel_launch(void* const* d_in, const int* in_sizes, int n_in,
                              void* d_out, int out_size) {
    const float* x  = (const float*)d_in[0];
    const int*   ei = (const int*)d_in[1];
    const float* W1 = (const float*)d_in[2];
    const float* b1 = (const float*)d_in[3];
    const float* W2 = (const float*)d_in[4];
    const float* b2 = (const float*)d_in[5];
    float* out = (float*)d_out;

    int N = in_sizes[0] / DD;
    int E = in_sizes[1] / 2;
    const int* src = ei;
    const int* dst = ei + E;

    float *dinv, *buf2;
    __half* hbuf;
    int *cnt, *rowptr, *cur, *col, *part;
    uint8_t *wb1, *wb2;
    cudaGetSymbolAddress((void**)&dinv, g_dinv);
    cudaGetSymbolAddress((void**)&hbuf, g_hbuf);
    cudaGetSymbolAddress((void**)&buf2, g_buf2);
    cudaGetSymbolAddress((void**)&cnt, g_cnt);
    cudaGetSymbolAddress((void**)&rowptr, g_rowptr);
    cudaGetSymbolAddress((void**)&cur, g_cur);
    cudaGetSymbolAddress((void**)&col, g_col);
    cudaGetSymbolAddress((void**)&part, g_part);
    cudaGetSymbolAddress((void**)&wb1, g_wb1);
    cudaGetSymbolAddress((void**)&wb2, g_wb2);

    // One-time resources (created on the first, uncaptured correctness call)
    static cudaStream_t s2 = nullptr;
    static cudaEvent_t evFork = nullptr, evJoin = nullptr;
    static bool smemSet = false;
    if (!s2) {
        cudaStreamCreateWithFlags(&s2, cudaStreamNonBlocking);
        cudaEventCreateWithFlags(&evFork, cudaEventDisableTiming);
        cudaEventCreateWithFlags(&evJoin, cudaEventDisableTiming);
    }
    if (!smemSet) {
        cudaFuncSetAttribute(k_gemm_mma, cudaFuncAttributeMaxDynamicSharedMemorySize,
                             GEMM_SMEM);
        smemSet = true;
    }

    const int T  = 256;
    int nb       = (N + 1023) / 1024;          // <= 64 partials
    int egrid4   = (E / 4 + T - 1) / T;        // 4 edges/thread kernels
    int gemm_grid   = (N + 127) / 128;
    int gather_grid = (N + 15) / 16;           // 8 warps/block, 2 nodes/warp

    // CSR build + normalization (+ fused W prep)
    cudaMemsetAsync(cnt, 0, (size_t)N * sizeof(int));
    k_hist_wprep<<<egrid4 + 128, T>>>(dst, cnt, E, egrid4, W1, wb1, W2, wb2);
    k_scan_partial<<<nb, T>>>(cnt, part, N);
    k_scan_down<<<nb, T>>>(cnt, part, rowptr, cur, dinv, N, nb);

    // Fork: CSR fill (side stream) in parallel with layer-1 GEMM (main stream)
    cudaEventRecord(evFork, 0);
    cudaStreamWaitEvent(s2, evFork, 0);
    k_fill<<<egrid4, T, 0, s2>>>(src, dst, cur, col, E);
    cudaEventRecord(evJoin, s2);

    k_gemm_mma<<<gemm_grid, 256, GEMM_SMEM>>>(x, wb1, dinv, hbuf, N);

    // Join before gather-1 (needs both col[] and hbuf)
    cudaStreamWaitEvent(0, evJoin, 0);

    k_gather<<<gather_grid, 256>>>(hbuf, rowptr, col, dinv, b1, buf2, N);

    // Layer 2
    k_gemm_mma<<<gemm_grid, 256, GEMM_SMEM>>>(buf2, wb2, dinv, hbuf, N);
    k_gather<<<gather_grid, 256>>>(hbuf, rowptr, col, dinv, b2, out, N);
}

// round 15
// speedup vs baseline: 1.0932x; 1.0063x over previous
#include <cuda_runtime.h>
#include <cuda_bf16.h>
#include <cuda_fp16.h>
#include <math.h>
#include <stdint.h>

#define DD   128
#define MAXN 50000
#define MAXE 800000

// Scratch (allocation-free rule: __device__ globals)
__device__ __align__(16) float   g_dinv[MAXN];
__device__ __align__(16) __half  g_hbuf[(size_t)MAXN * DD];  // fp16 messages
__device__ __align__(16) __half  g_abuf[(size_t)MAXN * DD];  // fp16 activations
__device__ __align__(16) int     g_cnt[MAXN];
__device__ __align__(16) int     g_rowptr[MAXN + 4];
__device__ __align__(16) int     g_cur[MAXN];
__device__ __align__(16) int     g_col[MAXE];
__device__ __align__(16) int     g_part[64];
// Pre-split/transposed/swizzled W images (one per layer):
// [kh0: Bhi 16KB | Blo 16KB][kh1: Bhi 16KB | Blo 16KB]  (Bt[n][k] bf16, SW128)
__device__ __align__(16) uint8_t g_wb1[65536];
__device__ __align__(16) uint8_t g_wb2[65536];

// ---------------------------------------------------------------------------
// Helpers (sm_80+ only: ldmatrix + mma.sync — NO tcgen05, target is sm_103)
// ---------------------------------------------------------------------------
__device__ __forceinline__ uint32_t swz128(uint32_t off) {
    return off ^ ((off >> 3) & 0x70);
}
__device__ __forceinline__ uint32_t smem_u32(const void* p) {
    return (uint32_t)__cvta_generic_to_shared(p);
}

__device__ __forceinline__ void ldsm_x4(uint32_t& r0, uint32_t& r1,
                                        uint32_t& r2, uint32_t& r3, uint32_t addr) {
    asm volatile("ldmatrix.sync.aligned.m8n8.x4.shared.b16 {%0,%1,%2,%3}, [%4];"
                 : "=r"(r0), "=r"(r1), "=r"(r2), "=r"(r3) : "r"(addr));
}
__device__ __forceinline__ void ldsm_x2(uint32_t& r0, uint32_t& r1, uint32_t addr) {
    asm volatile("ldmatrix.sync.aligned.m8n8.x2.shared.b16 {%0,%1}, [%2];"
                 : "=r"(r0), "=r"(r1) : "r"(addr));
}
__device__ __forceinline__ void mma_bf16(float& d0, float& d1, float& d2, float& d3,
                                         uint32_t a0, uint32_t a1, uint32_t a2, uint32_t a3,
                                         uint32_t b0, uint32_t b1) {
    asm volatile(
        "mma.sync.aligned.m16n8k16.row.col.f32.bf16.bf16.f32 "
        "{%0,%1,%2,%3}, {%4,%5,%6,%7}, {%8,%9}, {%0,%1,%2,%3};"
        : "+f"(d0), "+f"(d1), "+f"(d2), "+f"(d3)
        : "r"(a0), "r"(a1), "r"(a2), "r"(a3), "r"(b0), "r"(b1));
}

// ---------------------------------------------------------------------------
// W split helper (shared by the fused hist+wprep kernel)
// ---------------------------------------------------------------------------
__device__ __forceinline__ void wprep_one(const float* __restrict__ W,
                                          uint8_t* __restrict__ wb, int idx) {
    int nn = idx & 127;           // output col -> Bt row
    int k  = idx >> 7;            // input dim  -> Bt col
    float v = W[k * DD + nn];
    __nv_bfloat16 hi = __float2bfloat16(v);
    __nv_bfloat16 lo = __float2bfloat16(v - __bfloat162float(hi));
    int half = k >> 6, kk = k & 63;
    uint32_t off = swz128((uint32_t)(nn * 128 + kk * 2));
    *(__nv_bfloat16*)(wb + half * 32768 + off)         = hi;
    *(__nv_bfloat16*)(wb + half * 32768 + 16384 + off) = lo;
}

// ---------------------------------------------------------------------------
// Fused: histogram of dst (blocks < eb, 4 edges/thread) + W1/W2 prep
// ---------------------------------------------------------------------------
__global__ void k_hist_wprep(const int* __restrict__ dst, int* __restrict__ cnt,
                             int E, int eb,
                             const float* __restrict__ W1, uint8_t* __restrict__ wb1,
                             const float* __restrict__ W2, uint8_t* __restrict__ wb2) {
    int b = blockIdx.x;
    if (b < eb) {
        int i = (b * blockDim.x + threadIdx.x) * 4;
        if (i + 3 < E) {
            int4 d = *(const int4*)(dst + i);
            atomicAdd(&cnt[d.x], 1);
            atomicAdd(&cnt[d.y], 1);
            atomicAdd(&cnt[d.z], 1);
            atomicAdd(&cnt[d.w], 1);
        } else {
            for (int j = 0; j < 4; j++)
                if (i + j < E) atomicAdd(&cnt[dst[i + j]], 1);
        }
    } else if (b < eb + 64) {
        wprep_one(W1, wb1, (b - eb) * 256 + threadIdx.x);
    } else {
        wprep_one(W2, wb2, (b - eb - 64) * 256 + threadIdx.x);
    }
}

// ---------------------------------------------------------------------------
// 2-phase exclusive scan (+ dinv epilogue). Phase 1: per-block (1024) sums.
// ---------------------------------------------------------------------------
__global__ __launch_bounds__(256) void k_scan_partial(const int* __restrict__ cnt,
                                                      int* __restrict__ part, int n) {
    __shared__ int sh[8];
    int tid  = threadIdx.x;
    int base = blockIdx.x * 1024 + tid * 4;
    int s = 0;
    if (base + 3 < n) {
        int4 v = *(const int4*)(cnt + base);
        s = v.x + v.y + v.z + v.w;
    } else {
        for (int j = 0; j < 4; j++)
            if (base + j < n) s += cnt[base + j];
    }
#pragma unroll
    for (int o = 16; o; o >>= 1) s += __shfl_down_sync(0xffffffffu, s, o);
    if ((tid & 31) == 0) sh[tid >> 5] = s;
    __syncthreads();
    if (tid < 8) {
        s = sh[tid];
#pragma unroll
        for (int o = 4; o; o >>= 1) s += __shfl_down_sync(0x000000ffu, s, o);
        if (tid == 0) part[blockIdx.x] = s;
    }
}

// Phase 2 (fused tops-scan): every block redundantly scans the <=64 partials
// in-register, takes its own exclusive offset, then does the downsweep.
__global__ __launch_bounds__(256) void k_scan_down(const int* __restrict__ cnt,
                                                   const int* __restrict__ part,
                                                   int* __restrict__ rowptr,
                                                   int* __restrict__ cur,
                                                   float* __restrict__ dinv,
                                                   int n, int nb) {
    __shared__ int wsum[8];
    __shared__ int porig[64];
    __shared__ int pincl[64];
    int tid  = threadIdx.x;
    int lane = tid & 31, wid = tid >> 5;

    if (tid < 64) {
        int v = (tid < nb) ? part[tid] : 0;
        porig[tid] = v;
        int x = v;
#pragma unroll
        for (int o = 1; o < 32; o <<= 1) {
            int u = __shfl_up_sync(0xffffffffu, x, o);
            if (lane >= o) x += u;
        }
        pincl[tid] = x;
    }
    __syncthreads();
    int bi = blockIdx.x;
    int bincl = pincl[bi] + ((bi >= 32) ? pincl[31] : 0);
    int bexc  = bincl - porig[bi];
    if (bi == nb - 1 && tid == 0) rowptr[n] = bincl;

    int base = bi * 1024 + tid * 4;

    int4 c = make_int4(0, 0, 0, 0);
    if (base + 3 < n) c = *(const int4*)(cnt + base);
    else {
        int* cp = (int*)&c;
        for (int j = 0; j < 4; j++) cp[j] = (base + j < n) ? cnt[base + j] : 0;
    }
    int s0 = c.x, s1 = s0 + c.y, s2 = s1 + c.z, s3 = s2 + c.w;
    int ts = s3, sc = ts;
#pragma unroll
    for (int o = 1; o < 32; o <<= 1) {
        int u = __shfl_up_sync(0xffffffffu, sc, o);
        if (lane >= o) sc += u;
    }
    if (lane == 31) wsum[wid] = sc;
    __syncthreads();
    if (wid == 0) {
        int w = (lane < 8) ? wsum[lane] : 0;
#pragma unroll
        for (int o = 1; o < 8; o <<= 1) {
            int u = __shfl_up_sync(0xffffffffu, w, o);
            if (lane >= o) w += u;
        }
        if (lane < 8) wsum[lane] = w;
    }
    __syncthreads();

    int off = bexc + (wid ? wsum[wid - 1] : 0) + (sc - ts);
    if (base + 3 < n) {
        int4 r = make_int4(off, off + s0, off + s1, off + s2);
        *(int4*)(rowptr + base) = r;
        *(int4*)(cur + base)    = r;
        float4 dv = make_float4(rsqrtf((float)(c.x + 1)), rsqrtf((float)(c.y + 1)),
                                rsqrtf((float)(c.z + 1)), rsqrtf((float)(c.w + 1)));
        *(float4*)(dinv + base) = dv;
    } else {
        int rr[4] = {off, off + s0, off + s1, off + s2};
        int* cp = (int*)&c;
        for (int j = 0; j < 4; j++)
            if (base + j < n) {
                rowptr[base + j] = rr[j];
                cur[base + j]    = rr[j];
                dinv[base + j]   = rsqrtf((float)(cp[j] + 1));
            }
    }
}

// ---------------------------------------------------------------------------
// CSR fill — standalone (no smem, high occupancy), 4 edges/thread
// ---------------------------------------------------------------------------
__global__ void k_fill(const int* __restrict__ src, const int* __restrict__ dst,
                       int* __restrict__ cur, int* __restrict__ col, int E) {
    int i = (blockIdx.x * blockDim.x + threadIdx.x) * 4;
    if (i + 3 < E) {
        int4 s = *(const int4*)(src + i);
        int4 d = *(const int4*)(dst + i);
        int p0 = atomicAdd(&cur[d.x], 1);
        int p1 = atomicAdd(&cur[d.y], 1);
        int p2 = atomicAdd(&cur[d.z], 1);
        int p3 = atomicAdd(&cur[d.w], 1);
        col[p0] = s.x; col[p1] = s.y; col[p2] = s.z; col[p3] = s.w;
    } else {
        for (int j = 0; j < 4; j++)
            if (i + j < E) col[atomicAdd(&cur[dst[i + j]], 1)] = src[i + j];
    }
}

// ---------------------------------------------------------------------------
// A-tile loaders: fp32 (layer 1) and fp16 (layer 2, exact under bf16 hi/lo)
// ---------------------------------------------------------------------------
__device__ __forceinline__ float4 load_a4(const float* A, size_t row, int kh, int f4) {
    return ((const float4*)A)[row * 32 + (size_t)kh * 16 + f4];
}
__device__ __forceinline__ float4 load_a4(const __half* A, size_t row, int kh, int f4) {
    uint2 u = ((const uint2*)A)[row * 32 + (size_t)kh * 16 + f4];
    float2 f0 = __half22float2(*(const __half2*)&u.x);
    float2 f1 = __half22float2(*(const __half2*)&u.y);
    return make_float4(f0.x, f0.y, f1.x, f1.y);
}

// ---------------------------------------------------------------------------
// GEMM device body (split bf16 via mma.sync, fp32 accum, fp16 out)
// ---------------------------------------------------------------------------
template <typename AT>
__device__ void gemm_body(char* sm, uint32_t sbase, int bid,
                          const AT* __restrict__ A, const uint8_t* __restrict__ wb,
                          const float* __restrict__ dinv, __half* __restrict__ Ch,
                          int n) {
    int tid  = threadIdx.x;
    int wid  = tid >> 5, lane = tid & 31;
    int row0 = bid * 128;

    int mrow0 = (wid & 3) * 32;
    int ncol0 = (wid >> 2) * 64;

    float acc[2][8][4];
#pragma unroll
    for (int i = 0; i < 2; i++)
#pragma unroll
        for (int j = 0; j < 8; j++)
#pragma unroll
            for (int q = 0; q < 4; q++) acc[i][j][q] = 0.0f;

    for (int kh = 0; kh < 2; kh++) {
        const float4* wb4 = (const float4*)(wb + kh * 32768);
#pragma unroll
        for (int t = 0; t < 8; t++) {
            int i = tid + t * 256;
            *(float4*)(sm + 32768 + i * 16) = wb4[i];
        }
#pragma unroll
        for (int t = 0; t < 8; t++) {
            int i  = tid + t * 256;
            int m  = i >> 4;
            int f4 = i & 15;
            int gr = row0 + m;
            float4 v = (gr < n) ? load_a4(A, (size_t)gr, kh, f4)
                                : make_float4(0.f, 0.f, 0.f, 0.f);
            __nv_bfloat16 hx = __float2bfloat16(v.x);
            __nv_bfloat16 hy = __float2bfloat16(v.y);
            __nv_bfloat16 hz = __float2bfloat16(v.z);
            __nv_bfloat16 hw = __float2bfloat16(v.w);
            __nv_bfloat162 h0, h1, l0, l1;
            h0.x = hx; h0.y = hy; h1.x = hz; h1.y = hw;
            l0.x = __float2bfloat16(v.x - __bfloat162float(hx));
            l0.y = __float2bfloat16(v.y - __bfloat162float(hy));
            l1.x = __float2bfloat16(v.z - __bfloat162float(hz));
            l1.y = __float2bfloat16(v.w - __bfloat162float(hw));
            uint32_t off = swz128((uint32_t)(m * 128 + f4 * 8));
            *(__nv_bfloat162*)(sm + off)             = h0;
            *(__nv_bfloat162*)(sm + off + 4)         = h1;
            *(__nv_bfloat162*)(sm + 16384 + off)     = l0;
            *(__nv_bfloat162*)(sm + 16384 + off + 4) = l1;
        }
        __syncthreads();

#pragma unroll
        for (int k16 = 0; k16 < 4; k16++) {
            int kbyte = k16 * 32;
            uint32_t afh[2][4], afl[2][4];
#pragma unroll
            for (int mt = 0; mt < 2; mt++) {
                int mrow = mrow0 + mt * 16 + (lane & 7) + ((lane & 8) ? 8 : 0);
                int kb   = kbyte + ((lane & 16) ? 16 : 0);
                uint32_t a = sbase + swz128((uint32_t)(mrow * 128 + kb));
                ldsm_x4(afh[mt][0], afh[mt][1], afh[mt][2], afh[mt][3], a);
                ldsm_x4(afl[mt][0], afl[mt][1], afl[mt][2], afl[mt][3], a + 16384);
            }
#pragma unroll
            for (int nt = 0; nt < 8; nt++) {
                int nrow = ncol0 + nt * 8 + (lane & 7);
                int kb   = kbyte + ((lane & 8) ? 16 : 0);
                uint32_t baddr = sbase + 32768 + swz128((uint32_t)(nrow * 128 + kb));
                uint32_t bh0, bh1, bl0, bl1;
                ldsm_x2(bh0, bh1, baddr);
                ldsm_x2(bl0, bl1, baddr + 16384);
#pragma unroll
                for (int mt = 0; mt < 2; mt++) {
                    mma_bf16(acc[mt][nt][0], acc[mt][nt][1], acc[mt][nt][2], acc[mt][nt][3],
                             afh[mt][0], afh[mt][1], afh[mt][2], afh[mt][3], bh0, bh1);
                    mma_bf16(acc[mt][nt][0], acc[mt][nt][1], acc[mt][nt][2], acc[mt][nt][3],
                             afh[mt][0], afh[mt][1], afh[mt][2], afh[mt][3], bl0, bl1);
                    mma_bf16(acc[mt][nt][0], acc[mt][nt][1], acc[mt][nt][2], acc[mt][nt][3],
                             afl[mt][0], afl[mt][1], afl[mt][2], afl[mt][3], bh0, bh1);
                }
            }
        }
        __syncthreads();
    }

#pragma unroll
    for (int mt = 0; mt < 2; mt++) {
        int r1 = row0 + mrow0 + mt * 16 + (lane >> 2);
        int r2 = r1 + 8;
        float s1 = (r1 < n) ? dinv[r1] : 0.f;
        float s2 = (r2 < n) ? dinv[r2] : 0.f;
#pragma unroll
        for (int nt = 0; nt < 8; nt++) {
            int col = ncol0 + nt * 8 + ((lane & 3) << 1);
            if (r1 < n)
                *(__half2*)(Ch + (size_t)r1 * DD + col) =
                    __floats2half2_rn(acc[mt][nt][0] * s1, acc[mt][nt][1] * s1);
            if (r2 < n)
                *(__half2*)(Ch + (size_t)r2 * DD + col) =
                    __floats2half2_rn(acc[mt][nt][2] * s2, acc[mt][nt][3] * s2);
        }
    }
}

static const uint32_t GEMM_SMEM = 65536;

__global__ void __launch_bounds__(256, 2)
k_gemm_f32(const float* __restrict__ A, const uint8_t* __restrict__ wb,
           const float* __restrict__ dinv, __half* __restrict__ Ch, int n) {
    extern __shared__ char sm[];
    gemm_body<float>(sm, smem_u32(sm), blockIdx.x, A, wb, dinv, Ch, n);
}

__global__ void __launch_bounds__(256, 2)
k_gemm_f16(const __half* __restrict__ A, const uint8_t* __restrict__ wb,
           const float* __restrict__ dinv, __half* __restrict__ Ch, int n) {
    extern __shared__ char sm[];
    gemm_body<__half>(sm, smem_u32(sm), blockIdx.x, A, wb, dinv, Ch, n);
}

// ---------------------------------------------------------------------------
// Fused CSR gather + self-loop + bias + ELU.  (round-9 proven shape)
// TWO nodes per warp: lanes 0-15 -> node 2w, lanes 16-31 -> node 2w+1.
// Lane owns a uint4 (8 halves = cols hl*8..hl*8+8). LDG.128 per edge.
// Output: float (final layer) or half (inter-layer activations).
// __launch_bounds__(256,6): push occupancy 5->6 blocks/SM (latency-edge kernel).
// ---------------------------------------------------------------------------
__device__ __forceinline__ float eluf(float x) { return x > 0.0f ? x : expm1f(x); }

__device__ __forceinline__ void acc_h8(float4& a0, float4& a1, uint4 u) {
    float2 f0 = __half22float2(*(const __half2*)&u.x);
    float2 f1 = __half22float2(*(const __half2*)&u.y);
    float2 f2 = __half22float2(*(const __half2*)&u.z);
    float2 f3 = __half22float2(*(const __half2*)&u.w);
    a0.x += f0.x; a0.y += f0.y; a0.z += f1.x; a0.w += f1.y;
    a1.x += f2.x; a1.y += f2.y; a1.z += f3.x; a1.w += f3.y;
}

__device__ __forceinline__ void store_gather(float* outp, size_t dd, int hl,
                                             float4 a0, float4 a1) {
    ((float4*)outp)[dd * 32 + hl * 2]     = a0;
    ((float4*)outp)[dd * 32 + hl * 2 + 1] = a1;
}
__device__ __forceinline__ void store_gather(__half* outp, size_t dd, int hl,
                                             float4 a0, float4 a1) {
    uint4 u;
    *(__half2*)&u.x = __floats2half2_rn(a0.x, a0.y);
    *(__half2*)&u.y = __floats2half2_rn(a0.z, a0.w);
    *(__half2*)&u.z = __floats2half2_rn(a1.x, a1.y);
    *(__half2*)&u.w = __floats2half2_rn(a1.z, a1.w);
    ((uint4*)outp)[dd * 16 + hl] = u;
}

template <typename OT>
__device__ void gather_body(const __half* __restrict__ hp,
                            const int* __restrict__ rowptr,
                            const int* __restrict__ colv,
                            const float* __restrict__ dinv,
                            const float* __restrict__ b,
                            OT* __restrict__ outp, int n) {
    int lane = threadIdx.x & 31;
    int half = lane >> 4;
    int hl   = lane & 15;
    int d    = (blockIdx.x * 8 + (threadIdx.x >> 5)) * 2 + half;
    uint32_t hmask = half ? 0xFFFF0000u : 0x0000FFFFu;

    bool valid = d < n;
    int dd     = valid ? d : 0;

    const uint4* hp4 = (const uint4*)hp;   // 16 uint4 (8 halves each) per row

    int start = rowptr[dd];
    int end   = valid ? rowptr[dd + 1] : start;

    float4 a0 = make_float4(0.f, 0.f, 0.f, 0.f);
    float4 a1 = make_float4(0.f, 0.f, 0.f, 0.f);
    acc_h8(a0, a1, hp4[(size_t)dd * 16 + hl]);   // self-loop

    for (int base = start; base < end; base += 16) {
        int cnt  = min(16, end - base);
        int sidx = (base + hl < end) ? colv[base + hl] : 0;
        int j = 0;
        for (; j + 4 <= cnt; j += 4) {
            int s0 = __shfl_sync(hmask, sidx, j,     16);
            int s1 = __shfl_sync(hmask, sidx, j + 1, 16);
            int s2 = __shfl_sync(hmask, sidx, j + 2, 16);
            int s3 = __shfl_sync(hmask, sidx, j + 3, 16);
            uint4 u0 = hp4[(size_t)s0 * 16 + hl];
            uint4 u1 = hp4[(size_t)s1 * 16 + hl];
            uint4 u2 = hp4[(size_t)s2 * 16 + hl];
            uint4 u3 = hp4[(size_t)s3 * 16 + hl];
            acc_h8(a0, a1, u0);
            acc_h8(a0, a1, u1);
            acc_h8(a0, a1, u2);
            acc_h8(a0, a1, u3);
        }
        for (; j < cnt; j++) {
            int s = __shfl_sync(hmask, sidx, j, 16);
            acc_h8(a0, a1, hp4[(size_t)s * 16 + hl]);
        }
    }

    if (valid) {
        float w = dinv[dd];
        float4 b0 = ((const float4*)b)[hl * 2];
        float4 b1 = ((const float4*)b)[hl * 2 + 1];
        a0.x = eluf(a0.x * w + b0.x);
        a0.y = eluf(a0.y * w + b0.y);
        a0.z = eluf(a0.z * w + b0.z);
        a0.w = eluf(a0.w * w + b0.w);
        a1.x = eluf(a1.x * w + b1.x);
        a1.y = eluf(a1.y * w + b1.y);
        a1.z = eluf(a1.z * w + b1.z);
        a1.w = eluf(a1.w * w + b1.w);
        store_gather(outp, (size_t)dd, hl, a0, a1);
    }
}

__global__ void __launch_bounds__(256, 6)
k_gather_h(const __half* __restrict__ hp, const int* __restrict__ rowptr,
           const int* __restrict__ colv, const float* __restrict__ dinv,
           const float* __restrict__ b, __half* __restrict__ outp, int n) {
    gather_body<__half>(hp, rowptr, colv, dinv, b, outp, n);
}

__global__ void __launch_bounds__(256, 6)
k_gather_f(const __half* __restrict__ hp, const int* __restrict__ rowptr,
           const int* __restrict__ colv, const float* __restrict__ dinv,
           const float* __restrict__ b, float* __restrict__ outp, int n) {
    gather_body<float>(hp, rowptr, colv, dinv, b, outp, n);
}

// ---------------------------------------------------------------------------
// Launch — fork-join: k_fill runs on a side stream in parallel with GEMM-1.
// ---------------------------------------------------------------------------
extern "C" void kernel_launch(void* const* d_in, const int* in_sizes, int n_in,
                              void* d_out, int out_size) {
    const float* x  = (const float*)d_in[0];
    const int*   ei = (const int*)d_in[1];
    const float* W1 = (const float*)d_in[2];
    const float* b1 = (const float*)d_in[3];
    const float* W2 = (const float*)d_in[4];
    const float* b2 = (const float*)d_in[5];
    float* out = (float*)d_out;

    int N = in_sizes[0] / DD;
    int E = in_sizes[1] / 2;
    const int* src = ei;
    const int* dst = ei + E;

    float* dinv;
    __half *hbuf, *abuf;
    int *cnt, *rowptr, *cur, *col, *part;
    uint8_t *wb1, *wb2;
    cudaGetSymbolAddress((void**)&dinv, g_dinv);
    cudaGetSymbolAddress((void**)&hbuf, g_hbuf);
    cudaGetSymbolAddress((void**)&abuf, g_abuf);
    cudaGetSymbolAddress((void**)&cnt, g_cnt);
    cudaGetSymbolAddress((void**)&rowptr, g_rowptr);
    cudaGetSymbolAddress((void**)&cur, g_cur);
    cudaGetSymbolAddress((void**)&col, g_col);
    cudaGetSymbolAddress((void**)&part, g_part);
    cudaGetSymbolAddress((void**)&wb1, g_wb1);
    cudaGetSymbolAddress((void**)&wb2, g_wb2);

    // One-time resources (created on the first, uncaptured correctness call)
    static cudaStream_t s2 = nullptr;
    static cudaEvent_t evFork = nullptr, evJoin = nullptr;
    static bool smemSet = false;
    if (!s2) {
        cudaStreamCreateWithFlags(&s2, cudaStreamNonBlocking);
        cudaEventCreateWithFlags(&evFork, cudaEventDisableTiming);
        cudaEventCreateWithFlags(&evJoin, cudaEventDisableTiming);
    }
    if (!smemSet) {
        cudaFuncSetAttribute(k_gemm_f32, cudaFuncAttributeMaxDynamicSharedMemorySize,
                             GEMM_SMEM);
        cudaFuncSetAttribute(k_gemm_f16, cudaFuncAttributeMaxDynamicSharedMemorySize,
                             GEMM_SMEM);
        smemSet = true;
    }

    const int T  = 256;
    int nb       = (N + 1023) / 1024;          // <= 64 partials
    int egrid4   = (E / 4 + T - 1) / T;        // 4 edges/thread kernels
    int gemm_grid   = (N + 127) / 128;
    int gather_grid = (N + 15) / 16;           // 8 warps/block, 2 nodes/warp

    // CSR build + normalization (+ fused W prep)
    cudaMemsetAsync(cnt, 0, (size_t)N * sizeof(int));
    k_hist_wprep<<<egrid4 + 128, T>>>(dst, cnt, E, egrid4, W1, wb1, W2, wb2);
    k_scan_partial<<<nb, T>>>(cnt, part, N);
    k_scan_down<<<nb, T>>>(cnt, part, rowptr, cur, dinv, N, nb);

    // Fork: CSR fill (side stream) in parallel with layer-1 GEMM (main stream)
    cudaEventRecord(evFork, 0);
    cudaStreamWaitEvent(s2, evFork, 0);
    k_fill<<<egrid4, T, 0, s2>>>(src, dst, cur, col, E);
    cudaEventRecord(evJoin, s2);

    k_gemm_f32<<<gemm_grid, 256, GEMM_SMEM>>>(x, wb1, dinv, hbuf, N);

    // Join before gather-1 (needs both col[] and hbuf)
    cudaStreamWaitEvent(0, evJoin, 0);

    k_gather_h<<<gather_grid, 256>>>(hbuf, rowptr, col, dinv, b1, abuf, N);

    // Layer 2
    k_gemm_f16<<<gemm_grid, 256, GEMM_SMEM>>>(abuf, wb2, dinv, hbuf, N);
    k_gather_f<<<gather_grid, 256>>>(hbuf, rowptr, col, dinv, b2, out, N);
}

// round 16
// speedup vs baseline: 1.1351x; 1.0383x over previous
#include <cuda_runtime.h>
#include <cuda_bf16.h>
#include <cuda_fp16.h>
#include <math.h>
#include <stdint.h>

#define DD   128
#define MAXN 50000
#define MAXE 800000

// Scratch (allocation-free rule: __device__ globals)
__device__ __align__(16) float   g_dinv[MAXN];
__device__ __align__(16) __half  g_hbuf[(size_t)MAXN * DD];  // fp16 messages
__device__ __align__(16) __half  g_abuf[(size_t)MAXN * DD];  // fp16 activations
__device__ __align__(16) int     g_cnt[MAXN];
__device__ __align__(16) int     g_rowptr[MAXN + 4];
__device__ __align__(16) int     g_cur[MAXN];
__device__ __align__(16) int     g_col[MAXE];
__device__ __align__(16) int     g_part[64];
// Pre-split/transposed/swizzled W images (one per layer):
// [kh0: Bhi 16KB | Blo 16KB][kh1: Bhi 16KB | Blo 16KB]  (Bt[n][k] bf16, SW128)
__device__ __align__(16) uint8_t g_wb1[65536];
__device__ __align__(16) uint8_t g_wb2[65536];

// ---------------------------------------------------------------------------
// Helpers (sm_80+ only: ldmatrix + mma.sync — NO tcgen05, target is sm_103)
// ---------------------------------------------------------------------------
__device__ __forceinline__ uint32_t swz128(uint32_t off) {
    return off ^ ((off >> 3) & 0x70);
}
__device__ __forceinline__ uint32_t smem_u32(const void* p) {
    return (uint32_t)__cvta_generic_to_shared(p);
}

__device__ __forceinline__ void ldsm_x4(uint32_t& r0, uint32_t& r1,
                                        uint32_t& r2, uint32_t& r3, uint32_t addr) {
    asm volatile("ldmatrix.sync.aligned.m8n8.x4.shared.b16 {%0,%1,%2,%3}, [%4];"
                 : "=r"(r0), "=r"(r1), "=r"(r2), "=r"(r3) : "r"(addr));
}
__device__ __forceinline__ void ldsm_x2(uint32_t& r0, uint32_t& r1, uint32_t addr) {
    asm volatile("ldmatrix.sync.aligned.m8n8.x2.shared.b16 {%0,%1}, [%2];"
                 : "=r"(r0), "=r"(r1) : "r"(addr));
}
__device__ __forceinline__ void mma_bf16(float& d0, float& d1, float& d2, float& d3,
                                         uint32_t a0, uint32_t a1, uint32_t a2, uint32_t a3,
                                         uint32_t b0, uint32_t b1) {
    asm volatile(
        "mma.sync.aligned.m16n8k16.row.col.f32.bf16.bf16.f32 "
        "{%0,%1,%2,%3}, {%4,%5,%6,%7}, {%8,%9}, {%0,%1,%2,%3};"
        : "+f"(d0), "+f"(d1), "+f"(d2), "+f"(d3)
        : "r"(a0), "r"(a1), "r"(a2), "r"(a3), "r"(b0), "r"(b1));
}

// ---------------------------------------------------------------------------
// W split helper (shared by the fused hist+wprep kernel)
// ---------------------------------------------------------------------------
__device__ __forceinline__ void wprep_one(const float* __restrict__ W,
                                          uint8_t* __restrict__ wb, int idx) {
    int nn = idx & 127;           // output col -> Bt row
    int k  = idx >> 7;            // input dim  -> Bt col
    float v = W[k * DD + nn];
    __nv_bfloat16 hi = __float2bfloat16(v);
    __nv_bfloat16 lo = __float2bfloat16(v - __bfloat162float(hi));
    int half = k >> 6, kk = k & 63;
    uint32_t off = swz128((uint32_t)(nn * 128 + kk * 2));
    *(__nv_bfloat16*)(wb + half * 32768 + off)         = hi;
    *(__nv_bfloat16*)(wb + half * 32768 + 16384 + off) = lo;
}

// ---------------------------------------------------------------------------
// Fused: histogram of dst (blocks < eb, 4 edges/thread) + W1/W2 prep
// ---------------------------------------------------------------------------
__global__ void k_hist_wprep(const int* __restrict__ dst, int* __restrict__ cnt,
                             int E, int eb,
                             const float* __restrict__ W1, uint8_t* __restrict__ wb1,
                             const float* __restrict__ W2, uint8_t* __restrict__ wb2) {
    int b = blockIdx.x;
    if (b < eb) {
        int i = (b * blockDim.x + threadIdx.x) * 4;
        if (i + 3 < E) {
            int4 d = *(const int4*)(dst + i);
            atomicAdd(&cnt[d.x], 1);
            atomicAdd(&cnt[d.y], 1);
            atomicAdd(&cnt[d.z], 1);
            atomicAdd(&cnt[d.w], 1);
        } else {
            for (int j = 0; j < 4; j++)
                if (i + j < E) atomicAdd(&cnt[dst[i + j]], 1);
        }
    } else if (b < eb + 64) {
        wprep_one(W1, wb1, (b - eb) * 256 + threadIdx.x);
    } else {
        wprep_one(W2, wb2, (b - eb - 64) * 256 + threadIdx.x);
    }
}

// ---------------------------------------------------------------------------
// dinv from histogram only (no scan dependency): dinv = rsqrt(cnt + 1)
// ---------------------------------------------------------------------------
__global__ void k_dinv(const int* __restrict__ cnt, float* __restrict__ dinv, int n) {
    int base = (blockIdx.x * blockDim.x + threadIdx.x) * 4;
    if (base + 3 < n) {
        int4 c = *(const int4*)(cnt + base);
        float4 dv = make_float4(rsqrtf((float)(c.x + 1)), rsqrtf((float)(c.y + 1)),
                                rsqrtf((float)(c.z + 1)), rsqrtf((float)(c.w + 1)));
        *(float4*)(dinv + base) = dv;
    } else {
        for (int j = 0; j < 4 && base + j < n; j++)
            dinv[base + j] = rsqrtf((float)(cnt[base + j] + 1));
    }
}

// ---------------------------------------------------------------------------
// 2-phase exclusive scan. Phase 1: per-block (1024) sums.
// ---------------------------------------------------------------------------
__global__ __launch_bounds__(256) void k_scan_partial(const int* __restrict__ cnt,
                                                      int* __restrict__ part, int n) {
    __shared__ int sh[8];
    int tid  = threadIdx.x;
    int base = blockIdx.x * 1024 + tid * 4;
    int s = 0;
    if (base + 3 < n) {
        int4 v = *(const int4*)(cnt + base);
        s = v.x + v.y + v.z + v.w;
    } else {
        for (int j = 0; j < 4; j++)
            if (base + j < n) s += cnt[base + j];
    }
#pragma unroll
    for (int o = 16; o; o >>= 1) s += __shfl_down_sync(0xffffffffu, s, o);
    if ((tid & 31) == 0) sh[tid >> 5] = s;
    __syncthreads();
    if (tid < 8) {
        s = sh[tid];
#pragma unroll
        for (int o = 4; o; o >>= 1) s += __shfl_down_sync(0x000000ffu, s, o);
        if (tid == 0) part[blockIdx.x] = s;
    }
}

// Phase 2 (fused tops-scan): every block redundantly scans the <=64 partials
// in-register, takes its own exclusive offset, then does the downsweep.
__global__ __launch_bounds__(256) void k_scan_down(const int* __restrict__ cnt,
                                                   const int* __restrict__ part,
                                                   int* __restrict__ rowptr,
                                                   int* __restrict__ cur,
                                                   int n, int nb) {
    __shared__ int wsum[8];
    __shared__ int porig[64];
    __shared__ int pincl[64];
    int tid  = threadIdx.x;
    int lane = tid & 31, wid = tid >> 5;

    if (tid < 64) {
        int v = (tid < nb) ? part[tid] : 0;
        porig[tid] = v;
        int x = v;
#pragma unroll
        for (int o = 1; o < 32; o <<= 1) {
            int u = __shfl_up_sync(0xffffffffu, x, o);
            if (lane >= o) x += u;
        }
        pincl[tid] = x;
    }
    __syncthreads();
    int bi = blockIdx.x;
    int bincl = pincl[bi] + ((bi >= 32) ? pincl[31] : 0);
    int bexc  = bincl - porig[bi];
    if (bi == nb - 1 && tid == 0) rowptr[n] = bincl;

    int base = bi * 1024 + tid * 4;

    int4 c = make_int4(0, 0, 0, 0);
    if (base + 3 < n) c = *(const int4*)(cnt + base);
    else {
        int* cp = (int*)&c;
        for (int j = 0; j < 4; j++) cp[j] = (base + j < n) ? cnt[base + j] : 0;
    }
    int s0 = c.x, s1 = s0 + c.y, s2 = s1 + c.z, s3 = s2 + c.w;
    int ts = s3, sc = ts;
#pragma unroll
    for (int o = 1; o < 32; o <<= 1) {
        int u = __shfl_up_sync(0xffffffffu, sc, o);
        if (lane >= o) sc += u;
    }
    if (lane == 31) wsum[wid] = sc;
    __syncthreads();
    if (wid == 0) {
        int w = (lane < 8) ? wsum[lane] : 0;
#pragma unroll
        for (int o = 1; o < 8; o <<= 1) {
            int u = __shfl_up_sync(0xffffffffu, w, o);
            if (lane >= o) w += u;
        }
        if (lane < 8) wsum[lane] = w;
    }
    __syncthreads();

    int off = bexc + (wid ? wsum[wid - 1] : 0) + (sc - ts);
    if (base + 3 < n) {
        int4 r = make_int4(off, off + s0, off + s1, off + s2);
        *(int4*)(rowptr + base) = r;
        *(int4*)(cur + base)    = r;
    } else {
        int rr[4] = {off, off + s0, off + s1, off + s2};
        for (int j = 0; j < 4; j++)
            if (base + j < n) {
                rowptr[base + j] = rr[j];
                cur[base + j]    = rr[j];
            }
    }
}

// ---------------------------------------------------------------------------
// CSR fill — standalone (no smem, high occupancy), 4 edges/thread
// ---------------------------------------------------------------------------
__global__ void k_fill(const int* __restrict__ src, const int* __restrict__ dst,
                       int* __restrict__ cur, int* __restrict__ col, int E) {
    int i = (blockIdx.x * blockDim.x + threadIdx.x) * 4;
    if (i + 3 < E) {
        int4 s = *(const int4*)(src + i);
        int4 d = *(const int4*)(dst + i);
        int p0 = atomicAdd(&cur[d.x], 1);
        int p1 = atomicAdd(&cur[d.y], 1);
        int p2 = atomicAdd(&cur[d.z], 1);
        int p3 = atomicAdd(&cur[d.w], 1);
        col[p0] = s.x; col[p1] = s.y; col[p2] = s.z; col[p3] = s.w;
    } else {
        for (int j = 0; j < 4; j++)
            if (i + j < E) col[atomicAdd(&cur[dst[i + j]], 1)] = src[i + j];
    }
}

// ---------------------------------------------------------------------------
// A-tile loaders: fp32 (layer 1) and fp16 (layer 2, exact under bf16 hi/lo)
// ---------------------------------------------------------------------------
__device__ __forceinline__ float4 load_a4(const float* A, size_t row, int kh, int f4) {
    return ((const float4*)A)[row * 32 + (size_t)kh * 16 + f4];
}
__device__ __forceinline__ float4 load_a4(const __half* A, size_t row, int kh, int f4) {
    uint2 u = ((const uint2*)A)[row * 32 + (size_t)kh * 16 + f4];
    float2 f0 = __half22float2(*(const __half2*)&u.x);
    float2 f1 = __half22float2(*(const __half2*)&u.y);
    return make_float4(f0.x, f0.y, f1.x, f1.y);
}

// ---------------------------------------------------------------------------
// GEMM device body (split bf16 via mma.sync, fp32 accum, fp16 out)
// ---------------------------------------------------------------------------
template <typename AT>
__device__ void gemm_body(char* sm, uint32_t sbase, int bid,
                          const AT* __restrict__ A, const uint8_t* __restrict__ wb,
                          const float* __restrict__ dinv, __half* __restrict__ Ch,
                          int n) {
    int tid  = threadIdx.x;
    int wid  = tid >> 5, lane = tid & 31;
    int row0 = bid * 128;

    int mrow0 = (wid & 3) * 32;
    int ncol0 = (wid >> 2) * 64;

    float acc[2][8][4];
#pragma unroll
    for (int i = 0; i < 2; i++)
#pragma unroll
        for (int j = 0; j < 8; j++)
#pragma unroll
            for (int q = 0; q < 4; q++) acc[i][j][q] = 0.0f;

    for (int kh = 0; kh < 2; kh++) {
        const float4* wb4 = (const float4*)(wb + kh * 32768);
#pragma unroll
        for (int t = 0; t < 8; t++) {
            int i = tid + t * 256;
            *(float4*)(sm + 32768 + i * 16) = wb4[i];
        }
#pragma unroll
        for (int t = 0; t < 8; t++) {
            int i  = tid + t * 256;
            int m  = i >> 4;
            int f4 = i & 15;
            int gr = row0 + m;
            float4 v = (gr < n) ? load_a4(A, (size_t)gr, kh, f4)
                                : make_float4(0.f, 0.f, 0.f, 0.f);
            __nv_bfloat16 hx = __float2bfloat16(v.x);
            __nv_bfloat16 hy = __float2bfloat16(v.y);
            __nv_bfloat16 hz = __float2bfloat16(v.z);
            __nv_bfloat16 hw = __float2bfloat16(v.w);
            __nv_bfloat162 h0, h1, l0, l1;
            h0.x = hx; h0.y = hy; h1.x = hz; h1.y = hw;
            l0.x = __float2bfloat16(v.x - __bfloat162float(hx));
            l0.y = __float2bfloat16(v.y - __bfloat162float(hy));
            l1.x = __float2bfloat16(v.z - __bfloat162float(hz));
            l1.y = __float2bfloat16(v.w - __bfloat162float(hw));
            uint32_t off = swz128((uint32_t)(m * 128 + f4 * 8));
            *(__nv_bfloat162*)(sm + off)             = h0;
            *(__nv_bfloat162*)(sm + off + 4)         = h1;
            *(__nv_bfloat162*)(sm + 16384 + off)     = l0;
            *(__nv_bfloat162*)(sm + 16384 + off + 4) = l1;
        }
        __syncthreads();

#pragma unroll
        for (int k16 = 0; k16 < 4; k16++) {
            int kbyte = k16 * 32;
            uint32_t afh[2][4], afl[2][4];
#pragma unroll
            for (int mt = 0; mt < 2; mt++) {
                int mrow = mrow0 + mt * 16 + (lane & 7) + ((lane & 8) ? 8 : 0);
                int kb   = kbyte + ((lane & 16) ? 16 : 0);
                uint32_t a = sbase + swz128((uint32_t)(mrow * 128 + kb));
                ldsm_x4(afh[mt][0], afh[mt][1], afh[mt][2], afh[mt][3], a);
                ldsm_x4(afl[mt][0], afl[mt][1], afl[mt][2], afl[mt][3], a + 16384);
            }
#pragma unroll
            for (int nt = 0; nt < 8; nt++) {
                int nrow = ncol0 + nt * 8 + (lane & 7);
                int kb   = kbyte + ((lane & 8) ? 16 : 0);
                uint32_t baddr = sbase + 32768 + swz128((uint32_t)(nrow * 128 + kb));
                uint32_t bh0, bh1, bl0, bl1;
                ldsm_x2(bh0, bh1, baddr);
                ldsm_x2(bl0, bl1, baddr + 16384);
#pragma unroll
                for (int mt = 0; mt < 2; mt++) {
                    mma_bf16(acc[mt][nt][0], acc[mt][nt][1], acc[mt][nt][2], acc[mt][nt][3],
                             afh[mt][0], afh[mt][1], afh[mt][2], afh[mt][3], bh0, bh1);
                    mma_bf16(acc[mt][nt][0], acc[mt][nt][1], acc[mt][nt][2], acc[mt][nt][3],
                             afh[mt][0], afh[mt][1], afh[mt][2], afh[mt][3], bl0, bl1);
                    mma_bf16(acc[mt][nt][0], acc[mt][nt][1], acc[mt][nt][2], acc[mt][nt][3],
                             afl[mt][0], afl[mt][1], afl[mt][2], afl[mt][3], bh0, bh1);
                }
            }
        }
        __syncthreads();
    }

#pragma unroll
    for (int mt = 0; mt < 2; mt++) {
        int r1 = row0 + mrow0 + mt * 16 + (lane >> 2);
        int r2 = r1 + 8;
        float s1 = (r1 < n) ? dinv[r1] : 0.f;
        float s2 = (r2 < n) ? dinv[r2] : 0.f;
#pragma unroll
        for (int nt = 0; nt < 8; nt++) {
            int col = ncol0 + nt * 8 + ((lane & 3) << 1);
            if (r1 < n)
                *(__half2*)(Ch + (size_t)r1 * DD + col) =
                    __floats2half2_rn(acc[mt][nt][0] * s1, acc[mt][nt][1] * s1);
            if (r2 < n)
                *(__half2*)(Ch + (size_t)r2 * DD + col) =
                    __floats2half2_rn(acc[mt][nt][2] * s2, acc[mt][nt][3] * s2);
        }
    }
}

static const uint32_t GEMM_SMEM = 65536;

__global__ void __launch_bounds__(256, 2)
k_gemm_f32(const float* __restrict__ A, const uint8_t* __restrict__ wb,
           const float* __restrict__ dinv, __half* __restrict__ Ch, int n) {
    extern __shared__ char sm[];
    gemm_body<float>(sm, smem_u32(sm), blockIdx.x, A, wb, dinv, Ch, n);
}

__global__ void __launch_bounds__(256, 2)
k_gemm_f16(const __half* __restrict__ A, const uint8_t* __restrict__ wb,
           const float* __restrict__ dinv, __half* __restrict__ Ch, int n) {
    extern __shared__ char sm[];
    gemm_body<__half>(sm, smem_u32(sm), blockIdx.x, A, wb, dinv, Ch, n);
}

// ---------------------------------------------------------------------------
// Fused CSR gather + self-loop + bias + ELU.  (round-9 proven shape)
// TWO nodes per warp: lanes 0-15 -> node 2w, lanes 16-31 -> node 2w+1.
// Lane owns a uint4 (8 halves = cols hl*8..hl*8+8). LDG.128 per edge.
// Output: float (final layer) or half (inter-layer activations).
// ---------------------------------------------------------------------------
__device__ __forceinline__ float eluf(float x) { return x > 0.0f ? x : expm1f(x); }

__device__ __forceinline__ void acc_h8(float4& a0, float4& a1, uint4 u) {
    float2 f0 = __half22float2(*(const __half2*)&u.x);
    float2 f1 = __half22float2(*(const __half2*)&u.y);
    float2 f2 = __half22float2(*(const __half2*)&u.z);
    float2 f3 = __half22float2(*(const __half2*)&u.w);
    a0.x += f0.x; a0.y += f0.y; a0.z += f1.x; a0.w += f1.y;
    a1.x += f2.x; a1.y += f2.y; a1.z += f3.x; a1.w += f3.y;
}

__device__ __forceinline__ void store_gather(float* outp, size_t dd, int hl,
                                             float4 a0, float4 a1) {
    ((float4*)outp)[dd * 32 + hl * 2]     = a0;
    ((float4*)outp)[dd * 32 + hl * 2 + 1] = a1;
}
__device__ __forceinline__ void store_gather(__half* outp, size_t dd, int hl,
                                             float4 a0, float4 a1) {
    uint4 u;
    *(__half2*)&u.x = __floats2half2_rn(a0.x, a0.y);
    *(__half2*)&u.y = __floats2half2_rn(a0.z, a0.w);
    *(__half2*)&u.z = __floats2half2_rn(a1.x, a1.y);
    *(__half2*)&u.w = __floats2half2_rn(a1.z, a1.w);
    ((uint4*)outp)[dd * 16 + hl] = u;
}

template <typename OT>
__device__ void gather_body(const __half* __restrict__ hp,
                            const int* __restrict__ rowptr,
                            const int* __restrict__ colv,
                            const float* __restrict__ dinv,
                            const float* __restrict__ b,
                            OT* __restrict__ outp, int n) {
    int lane = threadIdx.x & 31;
    int half = lane >> 4;
    int hl   = lane & 15;
    int d    = (blockIdx.x * 8 + (threadIdx.x >> 5)) * 2 + half;
    uint32_t hmask = half ? 0xFFFF0000u : 0x0000FFFFu;

    bool valid = d < n;
    int dd     = valid ? d : 0;

    const uint4* hp4 = (const uint4*)hp;   // 16 uint4 (8 halves each) per row

    int start = rowptr[dd];
    int end   = valid ? rowptr[dd + 1] : start;

    float4 a0 = make_float4(0.f, 0.f, 0.f, 0.f);
    float4 a1 = make_float4(0.f, 0.f, 0.f, 0.f);
    acc_h8(a0, a1, hp4[(size_t)dd * 16 + hl]);   // self-loop

    for (int base = start; base < end; base += 16) {
        int cnt  = min(16, end - base);
        int sidx = (base + hl < end) ? colv[base + hl] : 0;
        int j = 0;
        for (; j + 4 <= cnt; j += 4) {
            int s0 = __shfl_sync(hmask, sidx, j,     16);
            int s1 = __shfl_sync(hmask, sidx, j + 1, 16);
            int s2 = __shfl_sync(hmask, sidx, j + 2, 16);
            int s3 = __shfl_sync(hmask, sidx, j + 3, 16);
            uint4 u0 = hp4[(size_t)s0 * 16 + hl];
            uint4 u1 = hp4[(size_t)s1 * 16 + hl];
            uint4 u2 = hp4[(size_t)s2 * 16 + hl];
            uint4 u3 = hp4[(size_t)s3 * 16 + hl];
            acc_h8(a0, a1, u0);
            acc_h8(a0, a1, u1);
            acc_h8(a0, a1, u2);
            acc_h8(a0, a1, u3);
        }
        for (; j < cnt; j++) {
            int s = __shfl_sync(hmask, sidx, j, 16);
            acc_h8(a0, a1, hp4[(size_t)s * 16 + hl]);
        }
    }

    if (valid) {
        float w = dinv[dd];
        float4 b0 = ((const float4*)b)[hl * 2];
        float4 b1 = ((const float4*)b)[hl * 2 + 1];
        a0.x = eluf(a0.x * w + b0.x);
        a0.y = eluf(a0.y * w + b0.y);
        a0.z = eluf(a0.z * w + b0.z);
        a0.w = eluf(a0.w * w + b0.w);
        a1.x = eluf(a1.x * w + b1.x);
        a1.y = eluf(a1.y * w + b1.y);
        a1.z = eluf(a1.z * w + b1.z);
        a1.w = eluf(a1.w * w + b1.w);
        store_gather(outp, (size_t)dd, hl, a0, a1);
    }
}

__global__ void __launch_bounds__(256, 6)
k_gather_h(const __half* __restrict__ hp, const int* __restrict__ rowptr,
           const int* __restrict__ colv, const float* __restrict__ dinv,
           const float* __restrict__ b, __half* __restrict__ outp, int n) {
    gather_body<__half>(hp, rowptr, colv, dinv, b, outp, n);
}

__global__ void __launch_bounds__(256, 6)
k_gather_f(const __half* __restrict__ hp, const int* __restrict__ rowptr,
           const int* __restrict__ colv, const float* __restrict__ dinv,
           const float* __restrict__ b, float* __restrict__ outp, int n) {
    gather_body<float>(hp, rowptr, colv, dinv, b, outp, n);
}

// ---------------------------------------------------------------------------
// Launch — fork at hist: side stream does scan+scan_down+fill while the main
// stream does dinv + layer-1 GEMM. Join before gather-1.
// ---------------------------------------------------------------------------
extern "C" void kernel_launch(void* const* d_in, const int* in_sizes, int n_in,
                              void* d_out, int out_size) {
    const float* x  = (const float*)d_in[0];
    const int*   ei = (const int*)d_in[1];
    const float* W1 = (const float*)d_in[2];
    const float* b1 = (const float*)d_in[3];
    const float* W2 = (const float*)d_in[4];
    const float* b2 = (const float*)d_in[5];
    float* out = (float*)d_out;

    int N = in_sizes[0] / DD;
    int E = in_sizes[1] / 2;
    const int* src = ei;
    const int* dst = ei + E;

    float* dinv;
    __half *hbuf, *abuf;
    int *cnt, *rowptr, *cur, *col, *part;
    uint8_t *wb1, *wb2;
    cudaGetSymbolAddress((void**)&dinv, g_dinv);
    cudaGetSymbolAddress((void**)&hbuf, g_hbuf);
    cudaGetSymbolAddress((void**)&abuf, g_abuf);
    cudaGetSymbolAddress((void**)&cnt, g_cnt);
    cudaGetSymbolAddress((void**)&rowptr, g_rowptr);
    cudaGetSymbolAddress((void**)&cur, g_cur);
    cudaGetSymbolAddress((void**)&col, g_col);
    cudaGetSymbolAddress((void**)&part, g_part);
    cudaGetSymbolAddress((void**)&wb1, g_wb1);
    cudaGetSymbolAddress((void**)&wb2, g_wb2);

    // One-time resources (created on the first, uncaptured correctness call)
    static cudaStream_t s2 = nullptr;
    static cudaEvent_t evHist = nullptr, evJoin = nullptr;
    static bool smemSet = false;
    if (!s2) {
        cudaStreamCreateWithFlags(&s2, cudaStreamNonBlocking);
        cudaEventCreateWithFlags(&evHist, cudaEventDisableTiming);
        cudaEventCreateWithFlags(&evJoin, cudaEventDisableTiming);
    }
    if (!smemSet) {
        cudaFuncSetAttribute(k_gemm_f32, cudaFuncAttributeMaxDynamicSharedMemorySize,
                             GEMM_SMEM);
        cudaFuncSetAttribute(k_gemm_f16, cudaFuncAttributeMaxDynamicSharedMemorySize,
                             GEMM_SMEM);
        smemSet = true;
    }

    const int T  = 256;
    int nb       = (N + 1023) / 1024;          // <= 64 partials
    int egrid4   = (E / 4 + T - 1) / T;        // 4 edges/thread kernels
    int ngrid4   = (N / 4 + T - 1) / T;
    int gemm_grid   = (N + 127) / 128;
    int gather_grid = (N + 15) / 16;           // 8 warps/block, 2 nodes/warp

    // Histogram (+ fused W prep) on main stream
    cudaMemsetAsync(cnt, 0, (size_t)N * sizeof(int));
    k_hist_wprep<<<egrid4 + 128, T>>>(dst, cnt, E, egrid4, W1, wb1, W2, wb2);
    cudaEventRecord(evHist, 0);

    // Side stream: scan + fill (the long CSR tail)
    cudaStreamWaitEvent(s2, evHist, 0);
    k_scan_partial<<<nb, T, 0, s2>>>(cnt, part, N);
    k_scan_down<<<nb, T, 0, s2>>>(cnt, part, rowptr, cur, N, nb);
    k_fill<<<egrid4, T, 0, s2>>>(src, dst, cur, col, E);
    cudaEventRecord(evJoin, s2);

    // Main stream: dinv (hist-only dependency) + layer-1 GEMM, overlapping CSR
    k_dinv<<<ngrid4, T>>>(cnt, dinv, N);
    k_gemm_f32<<<gemm_grid, 256, GEMM_SMEM>>>(x, wb1, dinv, hbuf, N);

    // Join before gather-1 (needs col[] + rowptr + hbuf)
    cudaStreamWaitEvent(0, evJoin, 0);

    k_gather_h<<<gather_grid, 256>>>(hbuf, rowptr, col, dinv, b1, abuf, N);

    // Layer 2
    k_gemm_f16<<<gemm_grid, 256, GEMM_SMEM>>>(abuf, wb2, dinv, hbuf, N);
    k_gather_f<<<gather_grid, 256>>>(hbuf, rowptr, col, dinv, b2, out, N);
}